// round 1
// baseline (speedup 1.0000x reference)
#include <cuda_runtime.h>
#include <cstdint>

// ---------------------------------------------------------------------------
// Problem constants
// ---------------------------------------------------------------------------
#define T      6
#define H      40
#define W      72
#define C      512
#define NH     4
#define HD     128
#define WH_    5
#define WW_    9
#define NWH    8
#define NWW    8
#define NWIN   64
#define S_     45      // tokens per window per frame
#define NROLL  148
#define P_     180     // pooled tokens per frame (10*18)
#define KTOT   373     // 45 + 148 + 180
#define TKEYS  (T*KTOT) // 2238
#define TOK    (T*H*W)  // 17280
#define PTOK   (T*P_)   // 1080
#define SCALE  0.08838834764831845f  // 1/sqrt(128)

// ---------------------------------------------------------------------------
// Scratch (device globals — no allocation allowed)
// ---------------------------------------------------------------------------
__device__ float g_q [TOK * C];
__device__ float g_k [TOK * C];
__device__ float g_v [TOK * C];
__device__ float g_y [TOK * C];
__device__ float g_px[PTOK * C];
__device__ float g_pk[PTOK * C];
__device__ float g_pv[PTOK * C];
__device__ int   g_widx[NWIN * KTOT];
__device__ int   g_wmask[NWIN];

// ---------------------------------------------------------------------------
// GEMM: C[M,512] = A[M,512] @ B[512,512] + bias  (fp32, 64x64 tile, 4x4/thread)
// ---------------------------------------------------------------------------
__global__ __launch_bounds__(256) void gemm_bias_kernel(
    const float* __restrict__ A, const float* __restrict__ B,
    const float* __restrict__ bias, float* __restrict__ Cc, int M)
{
    const int N = 512, K = 512;
    __shared__ float As[16][68];
    __shared__ float Bs[16][64];
    int tid = threadIdx.x;
    int tx = tid & 15, ty = tid >> 4;
    int row0 = blockIdx.y * 64, col0 = blockIdx.x * 64;
    float acc[4][4] = {};
    int lm  = tid >> 2, lk4 = (tid & 3) * 4;
    int lbk = tid >> 4, lbn = (tid & 15) * 4;

    for (int k0 = 0; k0 < K; k0 += 16) {
        float4 a4 = make_float4(0.f, 0.f, 0.f, 0.f);
        if (row0 + lm < M)
            a4 = *(const float4*)(A + (size_t)(row0 + lm) * K + k0 + lk4);
        As[lk4 + 0][lm] = a4.x; As[lk4 + 1][lm] = a4.y;
        As[lk4 + 2][lm] = a4.z; As[lk4 + 3][lm] = a4.w;
        *(float4*)&Bs[lbk][lbn] =
            *(const float4*)(B + (size_t)(k0 + lbk) * N + col0 + lbn);
        __syncthreads();
#pragma unroll
        for (int k = 0; k < 16; k++) {
            float4 a = *(float4*)&As[k][ty * 4];
            float4 b = *(float4*)&Bs[k][tx * 4];
            float av[4] = {a.x, a.y, a.z, a.w};
            float bv[4] = {b.x, b.y, b.z, b.w};
#pragma unroll
            for (int i = 0; i < 4; i++)
#pragma unroll
                for (int j = 0; j < 4; j++) acc[i][j] += av[i] * bv[j];
        }
        __syncthreads();
    }
#pragma unroll
    for (int i = 0; i < 4; i++) {
        int r = row0 + ty * 4 + i;
        if (r < M) {
            float4 o;
            o.x = acc[i][0] + bias[col0 + tx * 4 + 0];
            o.y = acc[i][1] + bias[col0 + tx * 4 + 1];
            o.z = acc[i][2] + bias[col0 + tx * 4 + 2];
            o.w = acc[i][3] + bias[col0 + tx * 4 + 3];
            *(float4*)(Cc + (size_t)r * N + col0 + tx * 4) = o;
        }
    }
}

// ---------------------------------------------------------------------------
// Depthwise 4x4/stride-4 pool conv: x(6,40,72,512) -> g_px(6,10,18,512)
// ---------------------------------------------------------------------------
__global__ void pool_kernel(const float* __restrict__ x,
                            const float* __restrict__ pw,
                            const float* __restrict__ pb)
{
    int o = blockIdx.x;                 // f*180 + py*18 + px
    int f = o / 180, r = o % 180;
    int py = r / 18, pxx = r % 18;
    for (int c = threadIdx.x; c < C; c += blockDim.x) {
        float s = pb[c];
#pragma unroll
        for (int i = 0; i < 4; i++)
#pragma unroll
            for (int j = 0; j < 4; j++)
                s += x[((size_t)(f * H + py * 4 + i) * W + (pxx * 4 + j)) * C + c]
                     * pw[(i * 4 + j) * C + c];
        g_px[(size_t)o * C + c] = s;
    }
}

// ---------------------------------------------------------------------------
// Window mask: any nonzero mask element in window across frames
// ---------------------------------------------------------------------------
__global__ void wmask_kernel(const float* __restrict__ masks)
{
    int win = threadIdx.x;
    if (win >= NWIN) return;
    int wy = win >> 3, wx = win & 7;
    float s = 0.f;
    for (int f = 0; f < T; f++)
        for (int i = 0; i < WH_; i++)
            for (int j = 0; j < WW_; j++)
                s += masks[(size_t)(f * H + wy * WH_ + i) * W + (wx * WW_ + j)];
    g_wmask[win] = (s > 0.f) ? 1 : 0;
}

// ---------------------------------------------------------------------------
// Key index table: widx[win][j]  (j<45 window, 45..192 rolled, 193.. pooled<0)
// ---------------------------------------------------------------------------
__global__ void init_idx_kernel()
{
    __shared__ int vind[NROLL];
    if (threadIdx.x == 0) {
        int cnt = 0;
        for (int s = 0; s < 4; s++)
            for (int i = 0; i < WH_; i++)
                for (int j = 0; j < WW_; j++) {
                    bool inval;
                    if (s == 0)      inval = (i < 2 && j < 4);
                    else if (s == 1) inval = (i < 2 && j >= 5);
                    else if (s == 2) inval = (i >= 3 && j < 4);
                    else             inval = (i >= 3 && j >= 5);
                    if (!inval) vind[cnt++] = s * 45 + i * 9 + j;
                }
    }
    __syncthreads();
    int win = blockIdx.x;
    int wy = win >> 3, wx = win & 7;
    for (int j = threadIdx.x; j < KTOT; j += blockDim.x) {
        int val;
        if (j < S_) {
            int i = j / 9, jj = j % 9;
            val = (wy * WH_ + i) * W + (wx * WW_ + jj);
        } else if (j < S_ + NROLL) {
            int v = vind[j - S_];
            int s = v / 45, pos = v % 45;
            int i = pos / 9, jj = pos % 9;
            int s0 = (s < 2) ? -3 : 3;        // shifts: (-3,-5)(-3,5)(3,-5)(3,5)
            int s1 = ((s & 1) == 0) ? -5 : 5;
            int y = wy * WH_ + i, x = wx * WW_ + jj;
            int yy = ((y - s0) % H + H) % H;
            int xx = ((x - s1) % W + W) % W;
            val = yy * W + xx;
        } else {
            val = -(j - (S_ + NROLL)) - 1;    // pooled token p -> -(p+1)
        }
        g_widx[win * KTOT + j] = val;
    }
}

// ---------------------------------------------------------------------------
// Attention: one block per (win, head, frame). Streaming softmax, KC=64.
//   q tile 45x128 in smem, acc 45x128 in registers (3x4 per-thread tiles).
// ---------------------------------------------------------------------------
#define KC 64
#define SM_FLOATS (45*132 + 64*129 + 64*132 + 45*68)

__global__ __launch_bounds__(256, 2) void attn_kernel()
{
    const int win = blockIdx.x, head = blockIdx.y, frame = blockIdx.z;
    const int tid = threadIdx.x;
    extern __shared__ float sm[];
    float* q_s = sm;                       // [45][132]
    float* k_s = q_s + 45 * 132;           // [64][129]
    float* v_s = k_s + 64 * 129;           // [64][132]
    float* p_s = v_s + 64 * 132;           // [45][68]
    __shared__ float m_s[45], l_s[45], corr_s[45];

    const int wy = win >> 3, wx = win & 7;

    // load Q tile (pre-scaled)
    for (int e = tid; e < S_ * HD; e += 256) {
        int qi = e >> 7, d = e & 127;
        int y = wy * WH_ + qi / 9, x = wx * WW_ + qi % 9;
        size_t tok = (size_t)(frame * H + y) * W + x;
        q_s[qi * 132 + d] = g_q[tok * C + head * HD + d] * SCALE;
    }
    if (tid < S_) { m_s[tid] = -1e30f; l_s[tid] = 0.f; }

    float racc[2][12];
#pragma unroll
    for (int p = 0; p < 2; p++)
#pragma unroll
        for (int i = 0; i < 12; i++) racc[p][i] = 0.f;

    const int masked = g_wmask[win];
    const int nkeys  = masked ? TKEYS : S_;
    __syncthreads();

    for (int c0 = 0; c0 < nkeys; c0 += KC) {
        // ---- gather K/V chunk ----
        for (int e = tid; e < KC * HD; e += 256) {
            int kk = e >> 7, d = e & 127;
            int g = c0 + kk;
            float kv = 0.f, vv = 0.f;
            if (g < nkeys) {
                int f2, j;
                if (masked) { f2 = g / KTOT; j = g - f2 * KTOT; }
                else        { f2 = frame;    j = g; }
                int idx = g_widx[win * KTOT + j];
                if (idx >= 0) {
                    size_t off = ((size_t)(f2 * (H * W) + idx)) * C + head * HD + d;
                    kv = g_k[off]; vv = g_v[off];
                } else {
                    size_t off = ((size_t)(f2 * P_ + (-idx - 1))) * C + head * HD + d;
                    kv = g_pk[off]; vv = g_pv[off];
                }
            }
            k_s[kk * 129 + d] = kv;
            v_s[kk * 132 + d] = vv;
        }
        __syncthreads();

        // ---- scores: 45x64, 3x4 register tiles (kj = kg + 16*j) ----
        if (tid < 240) {
            int qg = tid >> 4, kg = tid & 15;
            int qi0 = qg * 3;
            float s[3][4] = {};
#pragma unroll 4
            for (int d = 0; d < HD; d++) {
                float a0 = q_s[(qi0 + 0) * 132 + d];
                float a1 = q_s[(qi0 + 1) * 132 + d];
                float a2 = q_s[(qi0 + 2) * 132 + d];
#pragma unroll
                for (int j = 0; j < 4; j++) {
                    float bb = k_s[(kg + 16 * j) * 129 + d];
                    s[0][j] += a0 * bb;
                    s[1][j] += a1 * bb;
                    s[2][j] += a2 * bb;
                }
            }
#pragma unroll
            for (int i = 0; i < 3; i++)
#pragma unroll
                for (int j = 0; j < 4; j++) {
                    int kj = kg + 16 * j;
                    p_s[(qi0 + i) * 68 + kj] =
                        (c0 + kj < nkeys) ? s[i][j] : -1e30f;
                }
        }
        __syncthreads();

        // ---- online softmax per row ----
        if (tid < S_) {
            float mold = m_s[tid];
            float cm = mold;
#pragma unroll 8
            for (int j = 0; j < KC; j++) cm = fmaxf(cm, p_s[tid * 68 + j]);
            float corr = __expf(mold - cm);
            float sum = 0.f;
#pragma unroll 8
            for (int j = 0; j < KC; j++) {
                float e2 = __expf(p_s[tid * 68 + j] - cm);
                p_s[tid * 68 + j] = e2;
                sum += e2;
            }
            m_s[tid] = cm;
            l_s[tid] = l_s[tid] * corr + sum;
            corr_s[tid] = corr;
        }
        __syncthreads();

        // ---- acc = acc*corr + P @ V  (3 rows x 4 cols per thread-tile) ----
#pragma unroll
        for (int pass = 0; pass < 2; pass++) {
            int tt = tid + pass * 256;
            if (tt < 480) {
                int qg = tt >> 5, dg = tt & 31;
                int qi0 = qg * 3, d0 = dg * 4;
                float c0r = corr_s[qi0], c1r = corr_s[qi0 + 1], c2r = corr_s[qi0 + 2];
                float* r = racc[pass];
#pragma unroll
                for (int j = 0; j < 4; j++) { r[j] *= c0r; r[4 + j] *= c1r; r[8 + j] *= c2r; }
#pragma unroll 2
                for (int kk = 0; kk < KC; kk++) {
                    float p0 = p_s[(qi0 + 0) * 68 + kk];
                    float p1 = p_s[(qi0 + 1) * 68 + kk];
                    float p2 = p_s[(qi0 + 2) * 68 + kk];
                    float4 vv = *(float4*)&v_s[kk * 132 + d0];
                    r[0] += p0 * vv.x; r[1] += p0 * vv.y; r[2]  += p0 * vv.z; r[3]  += p0 * vv.w;
                    r[4] += p1 * vv.x; r[5] += p1 * vv.y; r[6]  += p1 * vv.z; r[7]  += p1 * vv.w;
                    r[8] += p2 * vv.x; r[9] += p2 * vv.y; r[10] += p2 * vv.z; r[11] += p2 * vv.w;
                }
            }
        }
        __syncthreads();
    }

    // ---- epilogue: y = acc / l ----
#pragma unroll
    for (int pass = 0; pass < 2; pass++) {
        int tt = tid + pass * 256;
        if (tt < 480) {
            int qg = tt >> 5, dg = tt & 31;
            int qi0 = qg * 3, d0 = dg * 4;
            float* r = racc[pass];
#pragma unroll
            for (int i = 0; i < 3; i++) {
                int qi = qi0 + i;
                float inv = 1.f / l_s[qi];
                int y = wy * WH_ + qi / 9, x = wx * WW_ + qi % 9;
                size_t tok = (size_t)(frame * H + y) * W + x;
                float4 o = make_float4(r[i * 4 + 0] * inv, r[i * 4 + 1] * inv,
                                       r[i * 4 + 2] * inv, r[i * 4 + 3] * inv);
                *(float4*)(g_y + tok * C + head * HD + d0) = o;
            }
        }
    }
}

// ---------------------------------------------------------------------------
// Launcher
// ---------------------------------------------------------------------------
extern "C" void kernel_launch(void* const* d_in, const int* in_sizes, int n_in,
                              void* d_out, int out_size)
{
    const float* x     = (const float*)d_in[0];
    const float* masks = (const float*)d_in[1];
    const float* Wq    = (const float*)d_in[2];
    const float* bq    = (const float*)d_in[3];
    const float* Wk    = (const float*)d_in[4];
    const float* bk    = (const float*)d_in[5];
    const float* Wv    = (const float*)d_in[6];
    const float* bv    = (const float*)d_in[7];
    const float* Wp    = (const float*)d_in[8];
    const float* bp    = (const float*)d_in[9];
    const float* pw    = (const float*)d_in[10];
    const float* pb    = (const float*)d_in[11];
    float* out = (float*)d_out;

    float *q, *k, *v, *y, *px, *pk, *pv;
    cudaGetSymbolAddress((void**)&q,  g_q);
    cudaGetSymbolAddress((void**)&k,  g_k);
    cudaGetSymbolAddress((void**)&v,  g_v);
    cudaGetSymbolAddress((void**)&y,  g_y);
    cudaGetSymbolAddress((void**)&px, g_px);
    cudaGetSymbolAddress((void**)&pk, g_pk);
    cudaGetSymbolAddress((void**)&pv, g_pv);

    const int smem_bytes = SM_FLOATS * sizeof(float);
    cudaFuncSetAttribute(attn_kernel,
                         cudaFuncAttributeMaxDynamicSharedMemorySize, smem_bytes);

    dim3 gBig(512 / 64, TOK / 64);     // (8, 270)
    dim3 gSm (512 / 64, (PTOK + 63) / 64); // (8, 17)

    gemm_bias_kernel<<<gBig, 256>>>(x, Wq, bq, q, TOK);
    gemm_bias_kernel<<<gBig, 256>>>(x, Wk, bk, k, TOK);
    gemm_bias_kernel<<<gBig, 256>>>(x, Wv, bv, v, TOK);

    pool_kernel<<<T * P_, 256>>>(x, pw, pb);
    gemm_bias_kernel<<<gSm, 256>>>(px, Wk, bk, pk, PTOK);
    gemm_bias_kernel<<<gSm, 256>>>(px, Wv, bv, pv, PTOK);

    wmask_kernel<<<1, 64>>>(masks);
    init_idx_kernel<<<NWIN, 128>>>();

    attn_kernel<<<dim3(NWIN, NH, T), 256, smem_bytes>>>();

    gemm_bias_kernel<<<gBig, 256>>>(y, Wp, bp, out, TOK);
}

// round 2
// speedup vs baseline: 3.2728x; 3.2728x over previous
#include <cuda_runtime.h>
#include <cstdint>

// ---------------------------------------------------------------------------
// Problem constants
// ---------------------------------------------------------------------------
#define T      6
#define H      40
#define W      72
#define C      512
#define NH     4
#define HD     128
#define WH_    5
#define WW_    9
#define NWIN   64
#define S_     45
#define NROLL  148
#define P_     180
#define KTOT   373
#define TKEYS  (T*KTOT)   // 2238
#define TOK    (T*H*W)    // 17280
#define PTOK   (T*P_)     // 1080
#define SCALE  0.08838834764831845f

// ---------------------------------------------------------------------------
// Scratch (device globals)
// ---------------------------------------------------------------------------
__device__ float g_q [TOK * C];
__device__ float g_k [TOK * C];
__device__ float g_v [TOK * C];
__device__ float g_y [TOK * C];
__device__ float g_xr[TOK * C];
__device__ float g_px[PTOK * C];
__device__ float g_pk[PTOK * C];
__device__ float g_pv[PTOK * C];
__device__ float g_wq[C * C];
__device__ float g_wk[C * C];
__device__ float g_wv[C * C];
__device__ float g_wp[C * C];
__device__ int   g_widx[NWIN * KTOT];
__device__ int   g_wmask[NWIN];

// ---------------------------------------------------------------------------
// Helpers
// ---------------------------------------------------------------------------
__device__ __forceinline__ float tf32r(float x) {
    unsigned u;
    asm("cvt.rna.tf32.f32 %0, %1;" : "=r"(u) : "f"(x));
    return __uint_as_float(u);
}

__device__ __forceinline__ void cpasync16(uint32_t dst, const void* src) {
    asm volatile("cp.async.cg.shared.global [%0], [%1], 16;\n"
                 :: "r"(dst), "l"(src));
}

__device__ __forceinline__ void mma_tf32(float* c, uint32_t a0, uint32_t a1,
                                         uint32_t a2, uint32_t a3,
                                         uint32_t b0, uint32_t b1) {
    asm volatile(
        "mma.sync.aligned.m16n8k8.row.col.f32.tf32.tf32.f32 "
        "{%0,%1,%2,%3}, {%4,%5,%6,%7}, {%8,%9}, {%0,%1,%2,%3};\n"
        : "+f"(c[0]), "+f"(c[1]), "+f"(c[2]), "+f"(c[3])
        : "r"(a0), "r"(a1), "r"(a2), "r"(a3), "r"(b0), "r"(b1));
}

// ---------------------------------------------------------------------------
// Round a tensor to tf32 (rna)
// ---------------------------------------------------------------------------
__global__ void round_kernel(const float* __restrict__ in,
                             float* __restrict__ out, int n4) {
    int i = blockIdx.x * blockDim.x + threadIdx.x;
    if (i < n4) {
        float4 v = ((const float4*)in)[i];
        v.x = tf32r(v.x); v.y = tf32r(v.y); v.z = tf32r(v.z); v.w = tf32r(v.w);
        ((float4*)out)[i] = v;
    }
}

// ---------------------------------------------------------------------------
// tf32 GEMM: C[M,512] = A[M,512] @ B[512,512] + bias
// 128x128x32 tiles, 8 warps (64x32 warp tiles), cp.async double buffer
// A smem [m][k] stride 36, B smem [k][n] stride 136 (conflict-free frags)
// ---------------------------------------------------------------------------
#define GAS 36
#define GBS 136
#define GEMM_SMEM ((2*128*GAS + 2*32*GBS) * 4)

__global__ __launch_bounds__(256) void gemm_tf32(
    const float* __restrict__ A, const float* __restrict__ B,
    const float* __restrict__ bias, float* __restrict__ Cc, int M, int round)
{
    extern __shared__ float sm[];
    float* As = sm;                   // [2][128][36]
    float* Bs = sm + 2 * 128 * GAS;   // [2][32][136]
    const int tid  = threadIdx.x;
    const int lane = tid & 31, warp = tid >> 5;
    const int grp  = lane >> 2, tg = lane & 3;
    const int m_base = (warp >> 2) * 64, n_base = (warp & 3) * 32;
    const int row0 = blockIdx.y * 128, col0 = blockIdx.x * 128;

    uint32_t s_as = (uint32_t)__cvta_generic_to_shared(As);
    uint32_t s_bs = (uint32_t)__cvta_generic_to_shared(Bs);

    const int arow = tid >> 1, acol = (tid & 1) * 16;
    const int brow = tid >> 3, bcol = (tid & 7) * 16;
    int agr = row0 + arow; if (agr > M - 1) agr = M - 1;
    const float* agp = A + (size_t)agr * 512 + acol;
    const float* bgp = B + (size_t)brow * 512 + col0 + bcol;
    uint32_t adst = s_as + (arow * GAS + acol) * 4;
    uint32_t bdst = s_bs + (brow * GBS + bcol) * 4;
    const uint32_t abuf = 128 * GAS * 4, bbuf = 32 * GBS * 4;

    float acc[4][4][4];
#pragma unroll
    for (int i = 0; i < 4; i++)
#pragma unroll
        for (int j = 0; j < 4; j++)
#pragma unroll
            for (int r = 0; r < 4; r++) acc[i][j][r] = 0.f;

    // stage 0
#pragma unroll
    for (int j = 0; j < 4; j++) cpasync16(adst + j * 16, agp + j * 4);
#pragma unroll
    for (int j = 0; j < 4; j++) cpasync16(bdst + j * 16, bgp + j * 4);
    asm volatile("cp.async.commit_group;\n");

    for (int it = 0; it < 16; ++it) {
        int buf = it & 1;
        if (it < 15) {
            int k0 = (it + 1) * 32;
            uint32_t ad = adst + (buf ^ 1) * abuf;
            uint32_t bd = bdst + (buf ^ 1) * bbuf;
#pragma unroll
            for (int j = 0; j < 4; j++) cpasync16(ad + j * 16, agp + k0 + j * 4);
#pragma unroll
            for (int j = 0; j < 4; j++)
                cpasync16(bd + j * 16, bgp + (size_t)k0 * 512 + j * 4);
            asm volatile("cp.async.commit_group;\n");
            asm volatile("cp.async.wait_group 1;\n");
        } else {
            asm volatile("cp.async.wait_group 0;\n");
        }
        __syncthreads();
        const float* a_s = As + buf * 128 * GAS;
        const float* b_s = Bs + buf * 32 * GBS;
#pragma unroll
        for (int k8 = 0; k8 < 4; k8++) {
            uint32_t af[4][4];
#pragma unroll
            for (int mt = 0; mt < 4; mt++) {
                const float* p = a_s + (m_base + mt * 16 + grp) * GAS + k8 * 8 + tg;
                af[mt][0] = __float_as_uint(p[0]);
                af[mt][1] = __float_as_uint(p[8 * GAS]);
                af[mt][2] = __float_as_uint(p[4]);
                af[mt][3] = __float_as_uint(p[8 * GAS + 4]);
            }
#pragma unroll
            for (int nt = 0; nt < 4; nt++) {
                const float* p = b_s + (k8 * 8 + tg) * GBS + n_base + nt * 8 + grp;
                uint32_t b0 = __float_as_uint(p[0]);
                uint32_t b1 = __float_as_uint(p[4 * GBS]);
#pragma unroll
                for (int mt = 0; mt < 4; mt++)
                    mma_tf32(acc[mt][nt], af[mt][0], af[mt][1], af[mt][2], af[mt][3], b0, b1);
            }
        }
        __syncthreads();
    }

    // epilogue
#pragma unroll
    for (int mt = 0; mt < 4; mt++) {
        int r0 = row0 + m_base + mt * 16 + grp;
#pragma unroll
        for (int nt = 0; nt < 4; nt++) {
            int cc = col0 + n_base + nt * 8 + tg * 2;
            float b0v = bias[cc], b1v = bias[cc + 1];
            float o0 = acc[mt][nt][0] + b0v, o1 = acc[mt][nt][1] + b1v;
            float o2 = acc[mt][nt][2] + b0v, o3 = acc[mt][nt][3] + b1v;
            if (round) { o0 = tf32r(o0); o1 = tf32r(o1); o2 = tf32r(o2); o3 = tf32r(o3); }
            if (r0 < M)     *(float2*)(Cc + (size_t)r0 * 512 + cc)       = make_float2(o0, o1);
            if (r0 + 8 < M) *(float2*)(Cc + (size_t)(r0 + 8) * 512 + cc) = make_float2(o2, o3);
        }
    }
}

// ---------------------------------------------------------------------------
// Depthwise 4x4/stride-4 pool conv -> tf32-rounded px
// ---------------------------------------------------------------------------
__global__ void pool_kernel(const float* __restrict__ x,
                            const float* __restrict__ pw,
                            const float* __restrict__ pb)
{
    int o = blockIdx.x;
    int f = o / 180, r = o % 180;
    int py = r / 18, pxx = r % 18;
    for (int c = threadIdx.x; c < C; c += blockDim.x) {
        float s = pb[c];
#pragma unroll
        for (int i = 0; i < 4; i++)
#pragma unroll
            for (int j = 0; j < 4; j++)
                s += x[((size_t)(f * H + py * 4 + i) * W + (pxx * 4 + j)) * C + c]
                     * pw[(i * 4 + j) * C + c];
        g_px[(size_t)o * C + c] = tf32r(s);
    }
}

// ---------------------------------------------------------------------------
// Window mask
// ---------------------------------------------------------------------------
__global__ void wmask_kernel(const float* __restrict__ masks)
{
    int win = threadIdx.x;
    if (win >= NWIN) return;
    int wy = win >> 3, wx = win & 7;
    float s = 0.f;
    for (int f = 0; f < T; f++)
        for (int i = 0; i < WH_; i++)
            for (int j = 0; j < WW_; j++)
                s += masks[(size_t)(f * H + wy * WH_ + i) * W + (wx * WW_ + j)];
    g_wmask[win] = (s > 0.f) ? 1 : 0;
}

// ---------------------------------------------------------------------------
// Key index table
// ---------------------------------------------------------------------------
__global__ void init_idx_kernel()
{
    __shared__ int vind[NROLL];
    if (threadIdx.x == 0) {
        int cnt = 0;
        for (int s = 0; s < 4; s++)
            for (int i = 0; i < WH_; i++)
                for (int j = 0; j < WW_; j++) {
                    bool inval;
                    if (s == 0)      inval = (i < 2 && j < 4);
                    else if (s == 1) inval = (i < 2 && j >= 5);
                    else if (s == 2) inval = (i >= 3 && j < 4);
                    else             inval = (i >= 3 && j >= 5);
                    if (!inval) vind[cnt++] = s * 45 + i * 9 + j;
                }
    }
    __syncthreads();
    int win = blockIdx.x;
    int wy = win >> 3, wx = win & 7;
    for (int j = threadIdx.x; j < KTOT; j += blockDim.x) {
        int val;
        if (j < S_) {
            int i = j / 9, jj = j % 9;
            val = (wy * WH_ + i) * W + (wx * WW_ + jj);
        } else if (j < S_ + NROLL) {
            int v = vind[j - S_];
            int s = v / 45, pos = v % 45;
            int i = pos / 9, jj = pos % 9;
            int s0 = (s < 2) ? -3 : 3;
            int s1 = ((s & 1) == 0) ? -5 : 5;
            int y = wy * WH_ + i, x = wx * WW_ + jj;
            int yy = ((y - s0) % H + H) % H;
            int xx = ((x - s1) % W + W) % W;
            val = yy * W + xx;
        } else {
            val = -(j - (S_ + NROLL)) - 1;
        }
        g_widx[win * KTOT + j] = val;
    }
}

// ---------------------------------------------------------------------------
// Attention: block=(win,head,frame), 128 threads / 4 warps, tf32 mma
// Q tile 48x128 (45 real), key chunks of 64, flash accumulators in c-frags
// ---------------------------------------------------------------------------
#define QS 132
#define KS 132
#define VS 136
#define PS 68
#define ATTN_SMEM ((48*QS + 64*KS + 64*VS + 48*PS) * 4)

__global__ __launch_bounds__(128, 2) void attn_tc()
{
    const int win = blockIdx.x, head = blockIdx.y, frame = blockIdx.z;
    const int tid  = threadIdx.x;
    const int lane = tid & 31, warp = tid >> 5;
    const int grp  = lane >> 2, tg = lane & 3;
    extern __shared__ float sm[];
    float* q_s = sm;                 // [48][132]
    float* k_s = q_s + 48 * QS;      // [64][132]
    float* v_s = k_s + 64 * KS;      // [64][136]
    float* p_s = v_s + 64 * VS;      // [48][68]
    __shared__ float m_s[48], l_s[48], corr_s[48];

    const int wy = win >> 3, wx = win & 7;

    for (int e = tid; e < 48 * 128; e += 128) {
        int row = e >> 7, d = e & 127;
        float v = 0.f;
        if (row < 45) {
            int y = wy * WH_ + row / 9, x = wx * WW_ + row % 9;
            v = g_q[((size_t)(frame * H + y) * W + x) * C + head * HD + d];
        }
        q_s[row * QS + d] = v;
    }
    if (tid < 48) { m_s[tid] = -1e30f; l_s[tid] = 0.f; corr_s[tid] = 1.f; }

    float acc[3][4][4];
#pragma unroll
    for (int i = 0; i < 3; i++)
#pragma unroll
        for (int j = 0; j < 4; j++)
#pragma unroll
            for (int r = 0; r < 4; r++) acc[i][j][r] = 0.f;

    const int masked = g_wmask[win];
    const int nkeys  = masked ? TKEYS : S_;
    const int* widx  = g_widx + win * KTOT;
    __syncthreads();

    for (int c0 = 0; c0 < nkeys; c0 += 64) {
        const int rem = nkeys - c0;

        // ---- gather K/V chunk (float4, coalesced, conflict-free STS) ----
#pragma unroll
        for (int i = 0; i < 16; i++) {
            int idx = i * 128 + tid;
            int key = idx >> 5, q4 = idx & 31;
            float4 kv = make_float4(0.f, 0.f, 0.f, 0.f), vv = kv;
            if (key < rem) {
                int g = c0 + key, f2, j;
                if (masked) { f2 = g / KTOT; j = g - f2 * KTOT; }
                else        { f2 = frame;    j = g; }
                int id = widx[j];
                size_t off;
                const float *kb, *vb;
                if (id >= 0) {
                    off = ((size_t)(f2 * (H * W) + id)) * C + head * HD + q4 * 4;
                    kb = g_k; vb = g_v;
                } else {
                    off = ((size_t)(f2 * P_ + (-id - 1))) * C + head * HD + q4 * 4;
                    kb = g_pk; vb = g_pv;
                }
                kv = *(const float4*)(kb + off);
                vv = *(const float4*)(vb + off);
            }
            *(float4*)&k_s[key * KS + q4 * 4] = kv;
            *(float4*)&v_s[key * VS + q4 * 4] = vv;
        }
        __syncthreads();

        // ---- QK^T: warp covers cols [warp*16, warp*16+16) ----
        {
            float c[3][2][4];
#pragma unroll
            for (int mt = 0; mt < 3; mt++)
#pragma unroll
                for (int nt = 0; nt < 2; nt++)
#pragma unroll
                    for (int r = 0; r < 4; r++) c[mt][nt][r] = 0.f;
#pragma unroll
            for (int k8 = 0; k8 < 16; k8++) {
                int dk = k8 * 8;
                uint32_t af[3][4];
#pragma unroll
                for (int mt = 0; mt < 3; mt++) {
                    const float* p = q_s + (mt * 16 + grp) * QS + dk + tg;
                    af[mt][0] = __float_as_uint(p[0]);
                    af[mt][1] = __float_as_uint(p[8 * QS]);
                    af[mt][2] = __float_as_uint(p[4]);
                    af[mt][3] = __float_as_uint(p[8 * QS + 4]);
                }
#pragma unroll
                for (int nt = 0; nt < 2; nt++) {
                    const float* p = k_s + (warp * 16 + nt * 8 + grp) * KS + dk + tg;
                    uint32_t b0 = __float_as_uint(p[0]);
                    uint32_t b1 = __float_as_uint(p[4]);
#pragma unroll
                    for (int mt = 0; mt < 3; mt++)
                        mma_tf32(c[mt][nt], af[mt][0], af[mt][1], af[mt][2], af[mt][3], b0, b1);
                }
            }
#pragma unroll
            for (int mt = 0; mt < 3; mt++)
#pragma unroll
                for (int nt = 0; nt < 2; nt++) {
                    int r0 = mt * 16 + grp, col = warp * 16 + nt * 8 + tg * 2;
                    *(float2*)&p_s[r0 * PS + col]       = make_float2(c[mt][nt][0], c[mt][nt][1]);
                    *(float2*)&p_s[(r0 + 8) * PS + col] = make_float2(c[mt][nt][2], c[mt][nt][3]);
                }
        }
        __syncthreads();

        // ---- online softmax (threads 0..95, row = tid>>1) ----
        if (tid < 96) {
            int row = tid >> 1, half = tid & 1;
            float* pr = p_s + row * PS + half * 32;
            int cbase = half * 32;
            float mold = m_s[row], cm = mold;
#pragma unroll
            for (int j = 0; j < 32; j++) {
                float s = (cbase + j < rem) ? pr[j] * SCALE : -1e30f;
                cm = fmaxf(cm, s);
            }
            cm = fmaxf(cm, __shfl_xor_sync(0xffffffffu, cm, 1));
            float corr = __expf(mold - cm);
            float sum = 0.f;
#pragma unroll
            for (int j = 0; j < 32; j++) {
                float e = (cbase + j < rem) ? __expf(pr[j] * SCALE - cm) : 0.f;
                sum += e;
                pr[j] = tf32r(e);
            }
            sum += __shfl_xor_sync(0xffffffffu, sum, 1);
            if (half == 0) {
                m_s[row] = cm;
                l_s[row] = l_s[row] * corr + sum;
                corr_s[row] = corr;
            }
        }
        __syncthreads();

        // ---- rescale accumulators + P @ V (warp covers d [warp*32, +32)) ----
#pragma unroll
        for (int mt = 0; mt < 3; mt++) {
            float cr0 = corr_s[mt * 16 + grp], cr1 = corr_s[mt * 16 + grp + 8];
#pragma unroll
            for (int nt = 0; nt < 4; nt++) {
                acc[mt][nt][0] *= cr0; acc[mt][nt][1] *= cr0;
                acc[mt][nt][2] *= cr1; acc[mt][nt][3] *= cr1;
            }
        }
#pragma unroll
        for (int k8 = 0; k8 < 8; k8++) {
            int kk = k8 * 8;
            uint32_t af[3][4];
#pragma unroll
            for (int mt = 0; mt < 3; mt++) {
                const float* p = p_s + (mt * 16 + grp) * PS + kk + tg;
                af[mt][0] = __float_as_uint(p[0]);
                af[mt][1] = __float_as_uint(p[8 * PS]);
                af[mt][2] = __float_as_uint(p[4]);
                af[mt][3] = __float_as_uint(p[8 * PS + 4]);
            }
#pragma unroll
            for (int nt = 0; nt < 4; nt++) {
                const float* p = v_s + (kk + tg) * VS + warp * 32 + nt * 8 + grp;
                uint32_t b0 = __float_as_uint(p[0]);
                uint32_t b1 = __float_as_uint(p[4 * VS]);
#pragma unroll
                for (int mt = 0; mt < 3; mt++)
                    mma_tf32(acc[mt][nt], af[mt][0], af[mt][1], af[mt][2], af[mt][3], b0, b1);
            }
        }
        __syncthreads();
    }

    // ---- epilogue: y = acc / l (tf32-rounded, feeds proj GEMM) ----
#pragma unroll
    for (int mt = 0; mt < 3; mt++) {
#pragma unroll
        for (int half = 0; half < 2; half++) {
            int r = mt * 16 + grp + half * 8;
            if (r < 45) {
                float inv = 1.f / l_s[r];
                int y = wy * WH_ + r / 9, x = wx * WW_ + r % 9;
                float* yp = g_y + ((size_t)(frame * H + y) * W + x) * C
                            + head * HD + warp * 32;
#pragma unroll
                for (int nt = 0; nt < 4; nt++) {
                    float o0 = tf32r(acc[mt][nt][half * 2 + 0] * inv);
                    float o1 = tf32r(acc[mt][nt][half * 2 + 1] * inv);
                    *(float2*)(yp + nt * 8 + tg * 2) = make_float2(o0, o1);
                }
            }
        }
    }
}

// ---------------------------------------------------------------------------
// Launcher
// ---------------------------------------------------------------------------
extern "C" void kernel_launch(void* const* d_in, const int* in_sizes, int n_in,
                              void* d_out, int out_size)
{
    const float* x     = (const float*)d_in[0];
    const float* masks = (const float*)d_in[1];
    const float* Wq    = (const float*)d_in[2];
    const float* bq    = (const float*)d_in[3];
    const float* Wk    = (const float*)d_in[4];
    const float* bk    = (const float*)d_in[5];
    const float* Wv    = (const float*)d_in[6];
    const float* bv    = (const float*)d_in[7];
    const float* Wp    = (const float*)d_in[8];
    const float* bp    = (const float*)d_in[9];
    const float* pw    = (const float*)d_in[10];
    const float* pb    = (const float*)d_in[11];
    float* out = (float*)d_out;

    float *q, *k, *v, *y, *xr, *px, *pk, *pv, *wq, *wk, *wv, *wp;
    cudaGetSymbolAddress((void**)&q,  g_q);
    cudaGetSymbolAddress((void**)&k,  g_k);
    cudaGetSymbolAddress((void**)&v,  g_v);
    cudaGetSymbolAddress((void**)&y,  g_y);
    cudaGetSymbolAddress((void**)&xr, g_xr);
    cudaGetSymbolAddress((void**)&px, g_px);
    cudaGetSymbolAddress((void**)&pk, g_pk);
    cudaGetSymbolAddress((void**)&pv, g_pv);
    cudaGetSymbolAddress((void**)&wq, g_wq);
    cudaGetSymbolAddress((void**)&wk, g_wk);
    cudaGetSymbolAddress((void**)&wv, g_wv);
    cudaGetSymbolAddress((void**)&wp, g_wp);

    cudaFuncSetAttribute(gemm_tf32, cudaFuncAttributeMaxDynamicSharedMemorySize, GEMM_SMEM);
    cudaFuncSetAttribute(attn_tc,   cudaFuncAttributeMaxDynamicSharedMemorySize, ATTN_SMEM);

    // tf32-round inputs that feed mma
    round_kernel<<<(TOK * C / 4 + 255) / 256, 256>>>(x, xr, TOK * C / 4);
    round_kernel<<<(C * C / 4 + 255) / 256, 256>>>(Wq, wq, C * C / 4);
    round_kernel<<<(C * C / 4 + 255) / 256, 256>>>(Wk, wk, C * C / 4);
    round_kernel<<<(C * C / 4 + 255) / 256, 256>>>(Wv, wv, C * C / 4);
    round_kernel<<<(C * C / 4 + 255) / 256, 256>>>(Wp, wp, C * C / 4);

    dim3 gBig(4, TOK / 128);                 // (4, 135)
    dim3 gSm (4, (PTOK + 127) / 128);        // (4, 9)

    gemm_tf32<<<gBig, 256, GEMM_SMEM>>>(xr, wq, bq, q, TOK, 1);
    gemm_tf32<<<gBig, 256, GEMM_SMEM>>>(xr, wk, bk, k, TOK, 1);
    gemm_tf32<<<gBig, 256, GEMM_SMEM>>>(xr, wv, bv, v, TOK, 1);

    pool_kernel<<<T * P_, 256>>>(x, pw, pb);
    gemm_tf32<<<gSm, 256, GEMM_SMEM>>>(px, wk, bk, pk, PTOK, 1);
    gemm_tf32<<<gSm, 256, GEMM_SMEM>>>(px, wv, bv, pv, PTOK, 1);

    wmask_kernel<<<1, 64>>>(masks);
    init_idx_kernel<<<NWIN, 128>>>();

    attn_tc<<<dim3(NWIN, NH, T), 128, ATTN_SMEM>>>();

    gemm_tf32<<<gBig, 256, GEMM_SMEM>>>(y, wp, bp, out, TOK, 0);
}

// round 4
// speedup vs baseline: 3.6772x; 1.1235x over previous
#include <cuda_runtime.h>
#include <cstdint>

// ---------------------------------------------------------------------------
// Problem constants
// ---------------------------------------------------------------------------
#define T      6
#define H      40
#define W      72
#define C      512
#define NH     4
#define HD     128
#define WH_    5
#define WW_    9
#define NWIN   64
#define S_     45
#define NROLL  148
#define P_     180
#define KTOT   373
#define TKEYS  (T*KTOT)   // 2238
#define TOK    (T*H*W)    // 17280
#define PTOK   (T*P_)     // 1080
#define SCALE  0.08838834764831845f

// ---------------------------------------------------------------------------
// Scratch (device globals)
// ---------------------------------------------------------------------------
__device__ float g_q [TOK * C];
__device__ float g_k [TOK * C];
__device__ float g_v [TOK * C];
__device__ float g_y [TOK * C];
__device__ float g_xr[TOK * C];
__device__ float g_px[PTOK * C];
__device__ float g_pk[PTOK * C];
__device__ float g_pv[PTOK * C];
__device__ float g_wq[C * C];
__device__ float g_wk[C * C];
__device__ float g_wv[C * C];
__device__ float g_wp[C * C];
__device__ int   g_widx[NWIN * KTOT];
__device__ int   g_wmask[NWIN];

// ---------------------------------------------------------------------------
// Helpers
// ---------------------------------------------------------------------------
__device__ __forceinline__ float tf32r(float x) {
    unsigned u;
    asm("cvt.rna.tf32.f32 %0, %1;" : "=r"(u) : "f"(x));
    return __uint_as_float(u);
}

__device__ __forceinline__ void cpasync16(uint32_t dst, const void* src) {
    asm volatile("cp.async.cg.shared.global [%0], [%1], 16;\n"
                 :: "r"(dst), "l"(src));
}

// zero-fill variant: copies src_sz bytes (0 or 16), zero-fills the rest
__device__ __forceinline__ void cpasync16z(uint32_t dst, const void* src, int src_sz) {
    asm volatile("cp.async.cg.shared.global [%0], [%1], 16, %2;\n"
                 :: "r"(dst), "l"(src), "r"(src_sz));
}

__device__ __forceinline__ void mma_tf32(float* c, uint32_t a0, uint32_t a1,
                                         uint32_t a2, uint32_t a3,
                                         uint32_t b0, uint32_t b1) {
    asm volatile(
        "mma.sync.aligned.m16n8k8.row.col.f32.tf32.tf32.f32 "
        "{%0,%1,%2,%3}, {%4,%5,%6,%7}, {%8,%9}, {%0,%1,%2,%3};\n"
        : "+f"(c[0]), "+f"(c[1]), "+f"(c[2]), "+f"(c[3])
        : "r"(a0), "r"(a1), "r"(a2), "r"(a3), "r"(b0), "r"(b1));
}

// ---------------------------------------------------------------------------
// Round tensors to tf32 (rna)
// ---------------------------------------------------------------------------
__global__ void round_kernel(const float* __restrict__ in,
                             float* __restrict__ out, int n4) {
    int i = blockIdx.x * blockDim.x + threadIdx.x;
    if (i < n4) {
        float4 v = ((const float4*)in)[i];
        v.x = tf32r(v.x); v.y = tf32r(v.y); v.z = tf32r(v.z); v.w = tf32r(v.w);
        ((float4*)out)[i] = v;
    }
}

// rounds the 4 weight matrices in one launch (blockIdx.y selects matrix)
__global__ void round_w_kernel(const float* __restrict__ w0, const float* __restrict__ w1,
                               const float* __restrict__ w2, const float* __restrict__ w3)
{
    const float* src[4] = {w0, w1, w2, w3};
    float* dst[4] = {g_wq, g_wk, g_wv, g_wp};
    int m = blockIdx.y;
    int i = blockIdx.x * blockDim.x + threadIdx.x;
    if (i < C * C / 4) {
        float4 v = ((const float4*)src[m])[i];
        v.x = tf32r(v.x); v.y = tf32r(v.y); v.z = tf32r(v.z); v.w = tf32r(v.w);
        ((float4*)dst[m])[i] = v;
    }
}

// ---------------------------------------------------------------------------
// tf32 GEMM: C[M,512] = A[M,512] @ B[512,512] + bias
// ---------------------------------------------------------------------------
#define GAS 36
#define GBS 136
#define GEMM_SMEM ((2*128*GAS + 2*32*GBS) * 4)

__global__ __launch_bounds__(256) void gemm_tf32(
    const float* __restrict__ A, const float* __restrict__ B,
    const float* __restrict__ bias, float* __restrict__ Cc, int M, int round)
{
    extern __shared__ float sm[];
    float* As = sm;
    float* Bs = sm + 2 * 128 * GAS;
    const int tid  = threadIdx.x;
    const int lane = tid & 31, warp = tid >> 5;
    const int grp  = lane >> 2, tg = lane & 3;
    const int m_base = (warp >> 2) * 64, n_base = (warp & 3) * 32;
    const int row0 = blockIdx.y * 128, col0 = blockIdx.x * 128;

    uint32_t s_as = (uint32_t)__cvta_generic_to_shared(As);
    uint32_t s_bs = (uint32_t)__cvta_generic_to_shared(Bs);

    const int arow = tid >> 1, acol = (tid & 1) * 16;
    const int brow = tid >> 3, bcol = (tid & 7) * 16;
    int agr = row0 + arow; if (agr > M - 1) agr = M - 1;
    const float* agp = A + (size_t)agr * 512 + acol;
    const float* bgp = B + (size_t)brow * 512 + col0 + bcol;
    uint32_t adst = s_as + (arow * GAS + acol) * 4;
    uint32_t bdst = s_bs + (brow * GBS + bcol) * 4;
    const uint32_t abuf = 128 * GAS * 4, bbuf = 32 * GBS * 4;

    float acc[4][4][4];
#pragma unroll
    for (int i = 0; i < 4; i++)
#pragma unroll
        for (int j = 0; j < 4; j++)
#pragma unroll
            for (int r = 0; r < 4; r++) acc[i][j][r] = 0.f;

#pragma unroll
    for (int j = 0; j < 4; j++) cpasync16(adst + j * 16, agp + j * 4);
#pragma unroll
    for (int j = 0; j < 4; j++) cpasync16(bdst + j * 16, bgp + j * 4);
    asm volatile("cp.async.commit_group;\n");

    for (int it = 0; it < 16; ++it) {
        int buf = it & 1;
        if (it < 15) {
            int k0 = (it + 1) * 32;
            uint32_t ad = adst + (buf ^ 1) * abuf;
            uint32_t bd = bdst + (buf ^ 1) * bbuf;
#pragma unroll
            for (int j = 0; j < 4; j++) cpasync16(ad + j * 16, agp + k0 + j * 4);
#pragma unroll
            for (int j = 0; j < 4; j++)
                cpasync16(bd + j * 16, bgp + (size_t)k0 * 512 + j * 4);
            asm volatile("cp.async.commit_group;\n");
            asm volatile("cp.async.wait_group 1;\n");
        } else {
            asm volatile("cp.async.wait_group 0;\n");
        }
        __syncthreads();
        const float* a_s = As + buf * 128 * GAS;
        const float* b_s = Bs + buf * 32 * GBS;
#pragma unroll
        for (int k8 = 0; k8 < 4; k8++) {
            uint32_t af[4][4];
#pragma unroll
            for (int mt = 0; mt < 4; mt++) {
                const float* p = a_s + (m_base + mt * 16 + grp) * GAS + k8 * 8 + tg;
                af[mt][0] = __float_as_uint(p[0]);
                af[mt][1] = __float_as_uint(p[8 * GAS]);
                af[mt][2] = __float_as_uint(p[4]);
                af[mt][3] = __float_as_uint(p[8 * GAS + 4]);
            }
#pragma unroll
            for (int nt = 0; nt < 4; nt++) {
                const float* p = b_s + (k8 * 8 + tg) * GBS + n_base + nt * 8 + grp;
                uint32_t b0 = __float_as_uint(p[0]);
                uint32_t b1 = __float_as_uint(p[4 * GBS]);
#pragma unroll
                for (int mt = 0; mt < 4; mt++)
                    mma_tf32(acc[mt][nt], af[mt][0], af[mt][1], af[mt][2], af[mt][3], b0, b1);
            }
        }
        __syncthreads();
    }

#pragma unroll
    for (int mt = 0; mt < 4; mt++) {
        int r0 = row0 + m_base + mt * 16 + grp;
#pragma unroll
        for (int nt = 0; nt < 4; nt++) {
            int cc = col0 + n_base + nt * 8 + tg * 2;
            float b0v = bias[cc], b1v = bias[cc + 1];
            float o0 = acc[mt][nt][0] + b0v, o1 = acc[mt][nt][1] + b1v;
            float o2 = acc[mt][nt][2] + b0v, o3 = acc[mt][nt][3] + b1v;
            if (round) { o0 = tf32r(o0); o1 = tf32r(o1); o2 = tf32r(o2); o3 = tf32r(o3); }
            if (r0 < M)     *(float2*)(Cc + (size_t)r0 * 512 + cc)       = make_float2(o0, o1);
            if (r0 + 8 < M) *(float2*)(Cc + (size_t)(r0 + 8) * 512 + cc) = make_float2(o2, o3);
        }
    }
}

// ---------------------------------------------------------------------------
// Depthwise 4x4/stride-4 pool conv -> tf32-rounded px
// ---------------------------------------------------------------------------
__global__ void pool_kernel(const float* __restrict__ x,
                            const float* __restrict__ pw,
                            const float* __restrict__ pb)
{
    int o = blockIdx.x;
    int f = o / 180, r = o % 180;
    int py = r / 18, pxx = r % 18;
    for (int c = threadIdx.x; c < C; c += blockDim.x) {
        float s = pb[c];
#pragma unroll
        for (int i = 0; i < 4; i++)
#pragma unroll
            for (int j = 0; j < 4; j++)
                s += x[((size_t)(f * H + py * 4 + i) * W + (pxx * 4 + j)) * C + c]
                     * pw[(i * 4 + j) * C + c];
        g_px[(size_t)o * C + c] = tf32r(s);
    }
}

// ---------------------------------------------------------------------------
// Window mask + key index table
// ---------------------------------------------------------------------------
__global__ void wmask_kernel(const float* __restrict__ masks)
{
    int win = threadIdx.x;
    if (win >= NWIN) return;
    int wy = win >> 3, wx = win & 7;
    float s = 0.f;
    for (int f = 0; f < T; f++)
        for (int i = 0; i < WH_; i++)
            for (int j = 0; j < WW_; j++)
                s += masks[(size_t)(f * H + wy * WH_ + i) * W + (wx * WW_ + j)];
    g_wmask[win] = (s > 0.f) ? 1 : 0;
}

__global__ void init_idx_kernel()
{
    __shared__ int vind[NROLL];
    if (threadIdx.x == 0) {
        int cnt = 0;
        for (int s = 0; s < 4; s++)
            for (int i = 0; i < WH_; i++)
                for (int j = 0; j < WW_; j++) {
                    bool inval;
                    if (s == 0)      inval = (i < 2 && j < 4);
                    else if (s == 1) inval = (i < 2 && j >= 5);
                    else if (s == 2) inval = (i >= 3 && j < 4);
                    else             inval = (i >= 3 && j >= 5);
                    if (!inval) vind[cnt++] = s * 45 + i * 9 + j;
                }
    }
    __syncthreads();
    int win = blockIdx.x;
    int wy = win >> 3, wx = win & 7;
    for (int j = threadIdx.x; j < KTOT; j += blockDim.x) {
        int val;
        if (j < S_) {
            int i = j / 9, jj = j % 9;
            val = (wy * WH_ + i) * W + (wx * WW_ + jj);
        } else if (j < S_ + NROLL) {
            int v = vind[j - S_];
            int s = v / 45, pos = v % 45;
            int i = pos / 9, jj = pos % 9;
            int s0 = (s < 2) ? -3 : 3;
            int s1 = ((s & 1) == 0) ? -5 : 5;
            int y = wy * WH_ + i, x = wx * WW_ + jj;
            int yy = ((y - s0) % H + H) % H;
            int xx = ((x - s1) % W + W) % W;
            val = yy * W + xx;
        } else {
            val = -(j - (S_ + NROLL)) - 1;
        }
        g_widx[win * KTOT + j] = val;
    }
}

// ---------------------------------------------------------------------------
// Attention v3: block=(win, head, frame-pair). 256 threads / 8 warps.
// Q tile 96 rows (2 frames x 48). KC=64, cp.async double-buffered K/V gather.
// Warp layout 2m x 4n: warp m = 48 rows (3 m16), QK n=16 keys, PV n=32 dims.
// ---------------------------------------------------------------------------
#define QS 132
#define KS 132
#define VS 136
#define PS 68
#define KC 64
#define ATTN_SMEM ((96*QS + 2*KC*KS + 2*KC*VS + 96*PS) * 4)

__global__ __launch_bounds__(256, 1) void attn_tc()
{
    const int win = blockIdx.x, head = blockIdx.y, fp = blockIdx.z;
    const int tid  = threadIdx.x;
    const int lane = tid & 31, warp = tid >> 5;
    const int grp  = lane >> 2, tg = lane & 3;
    const int m0   = (warp >> 2) * 48;         // 0 or 48
    const int nw   = warp & 3;                 // 0..3
    extern __shared__ float sm[];
    float* q_s = sm;                           // [96][132]
    float* k_s = q_s + 96 * QS;                // [2][64][132]
    float* v_s = k_s + 2 * KC * KS;            // [2][64][136]
    float* p_s = v_s + 2 * KC * VS;            // [96][68]
    __shared__ float m_s[96], l_s[96], corr_s[96];

    const int wy = win >> 3, wx = win & 7;
    const int masked = g_wmask[win];
    const int nch    = masked ? (TKEYS + KC - 1) / KC : 2;
    const int* widx  = g_widx + win * KTOT;

    // ---- load Q tile (96 rows = 2 frames x 48; rows 45-47/93-95 zero) ----
    for (int idx = tid; idx < 96 * 32; idx += 256) {
        int row = idx >> 5, q4 = idx & 31;
        int qi = row % 48;
        int frame = fp * 2 + (row >= 48 ? 1 : 0);
        float4 v = make_float4(0.f, 0.f, 0.f, 0.f);
        if (qi < 45) {
            int y = wy * WH_ + qi / 9, x = wx * WW_ + qi % 9;
            v = *(const float4*)(g_q + ((size_t)(frame * H + y) * W + x) * C
                                 + head * HD + q4 * 4);
        }
        *(float4*)&q_s[row * QS + q4 * 4] = v;
    }
    if (tid < 96) { m_s[tid] = -1e30f; l_s[tid] = 0.f; corr_s[tid] = 1.f; }

    float acc[3][4][4];
#pragma unroll
    for (int i = 0; i < 3; i++)
#pragma unroll
        for (int j = 0; j < 4; j++)
#pragma unroll
            for (int r = 0; r < 4; r++) acc[i][j][r] = 0.f;

    // ---- gather lambda: chunk cc into buffer buf via cp.async ----
    auto gather = [&](int buf, int cc) {
        uint32_t kb_s = (uint32_t)__cvta_generic_to_shared(k_s + buf * KC * KS);
        uint32_t vb_s = (uint32_t)__cvta_generic_to_shared(v_s + buf * KC * VS);
        int q4 = tid & 31;
#pragma unroll
        for (int i = 0; i < 8; i++) {
            int key = i * 8 + (tid >> 5);
            const float *ksrc = g_k, *vsrc = g_k;
            int sz = 0;
            bool valid;
            int f2, j;
            if (masked) {
                int g = cc * KC + key;
                valid = (g < TKEYS);
                f2 = g / KTOT; j = g - f2 * KTOT;
            } else {
                valid = (key < S_);
                f2 = fp * 2 + cc; j = key;
            }
            if (valid) {
                int id = widx[j];
                size_t off;
                if (id >= 0) {
                    off = ((size_t)(f2 * (H * W) + id)) * C + head * HD + q4 * 4;
                    ksrc = g_k + off; vsrc = g_v + off;
                } else {
                    off = ((size_t)(f2 * P_ + (-id - 1))) * C + head * HD + q4 * 4;
                    ksrc = g_pk + off; vsrc = g_pv + off;
                }
                sz = 16;
            }
            cpasync16z(kb_s + (key * KS + q4 * 4) * 4, ksrc, sz);
            cpasync16z(vb_s + (key * VS + q4 * 4) * 4, vsrc, sz);
        }
        asm volatile("cp.async.commit_group;\n");
    };

    gather(0, 0);
    __syncthreads();   // Q tile + m/l init visible

    for (int cc = 0; cc < nch; cc++) {
        int buf = cc & 1;
        if (cc + 1 < nch) {
            gather(buf ^ 1, cc + 1);
            asm volatile("cp.async.wait_group 1;\n");
        } else {
            asm volatile("cp.async.wait_group 0;\n");
        }
        __syncthreads();   // chunk cc data visible to all threads

        const float* kc_s = k_s + buf * KC * KS;
        const float* vc_s = v_s + buf * KC * VS;
        const int rem = masked ? min(KC, TKEYS - cc * KC) : S_;

        // ---- QK^T: 96 x 64 ----
        {
            float c[3][2][4];
#pragma unroll
            for (int mt = 0; mt < 3; mt++)
#pragma unroll
                for (int nt = 0; nt < 2; nt++)
#pragma unroll
                    for (int r = 0; r < 4; r++) c[mt][nt][r] = 0.f;
#pragma unroll
            for (int k8 = 0; k8 < 16; k8++) {
                int dk = k8 * 8;
                uint32_t af[3][4];
#pragma unroll
                for (int mt = 0; mt < 3; mt++) {
                    const float* p = q_s + (m0 + mt * 16 + grp) * QS + dk + tg;
                    af[mt][0] = __float_as_uint(p[0]);
                    af[mt][1] = __float_as_uint(p[8 * QS]);
                    af[mt][2] = __float_as_uint(p[4]);
                    af[mt][3] = __float_as_uint(p[8 * QS + 4]);
                }
#pragma unroll
                for (int nt = 0; nt < 2; nt++) {
                    const float* p = kc_s + (nw * 16 + nt * 8 + grp) * KS + dk + tg;
                    uint32_t b0 = __float_as_uint(p[0]);
                    uint32_t b1 = __float_as_uint(p[4]);
#pragma unroll
                    for (int mt = 0; mt < 3; mt++)
                        mma_tf32(c[mt][nt], af[mt][0], af[mt][1], af[mt][2], af[mt][3], b0, b1);
                }
            }
#pragma unroll
            for (int mt = 0; mt < 3; mt++)
#pragma unroll
                for (int nt = 0; nt < 2; nt++) {
                    int r0 = m0 + mt * 16 + grp, col = nw * 16 + nt * 8 + tg * 2;
                    *(float2*)&p_s[r0 * PS + col]       = make_float2(c[mt][nt][0], c[mt][nt][1]);
                    *(float2*)&p_s[(r0 + 8) * PS + col] = make_float2(c[mt][nt][2], c[mt][nt][3]);
                }
        }
        __syncthreads();

        // ---- online softmax (192 threads, 2 per row) ----
        if (tid < 192) {
            int row = tid >> 1, half = tid & 1;
            // unmasked path: row belongs to a frame; only chunk cc==frame idx valid
            bool rowok = masked || ((row >= 48 ? 1 : 0) == cc);
            float* pr = p_s + row * PS + half * 32;
            int cbase = half * 32;
            float mold = m_s[row], cm = mold;
#pragma unroll
            for (int j = 0; j < 32; j++) {
                float s = (rowok && cbase + j < rem) ? pr[j] * SCALE : -1e30f;
                cm = fmaxf(cm, s);
            }
            cm = fmaxf(cm, __shfl_xor_sync(0xffffffffu, cm, 1));
            float corr = __expf(mold - cm);
            float sum = 0.f;
#pragma unroll
            for (int j = 0; j < 32; j++) {
                float e = (rowok && cbase + j < rem) ? __expf(pr[j] * SCALE - cm) : 0.f;
                sum += e;
                pr[j] = tf32r(e);
            }
            sum += __shfl_xor_sync(0xffffffffu, sum, 1);
            if (half == 0) {
                m_s[row] = cm;
                l_s[row] = l_s[row] * corr + sum;
                corr_s[row] = corr;
            }
        }
        __syncthreads();

        // ---- rescale acc + P @ V (warp covers d [nw*32, +32)) ----
#pragma unroll
        for (int mt = 0; mt < 3; mt++) {
            float cr0 = corr_s[m0 + mt * 16 + grp], cr1 = corr_s[m0 + mt * 16 + grp + 8];
#pragma unroll
            for (int nt = 0; nt < 4; nt++) {
                acc[mt][nt][0] *= cr0; acc[mt][nt][1] *= cr0;
                acc[mt][nt][2] *= cr1; acc[mt][nt][3] *= cr1;
            }
        }
#pragma unroll
        for (int k8 = 0; k8 < 8; k8++) {
            int kk = k8 * 8;
            uint32_t af[3][4];
#pragma unroll
            for (int mt = 0; mt < 3; mt++) {
                const float* p = p_s + (m0 + mt * 16 + grp) * PS + kk + tg;
                af[mt][0] = __float_as_uint(p[0]);
                af[mt][1] = __float_as_uint(p[8 * PS]);
                af[mt][2] = __float_as_uint(p[4]);
                af[mt][3] = __float_as_uint(p[8 * PS + 4]);
            }
#pragma unroll
            for (int nt = 0; nt < 4; nt++) {
                const float* p = vc_s + (kk + tg) * VS + nw * 32 + nt * 8 + grp;
                uint32_t b0 = __float_as_uint(p[0]);
                uint32_t b1 = __float_as_uint(p[4 * VS]);
#pragma unroll
                for (int mt = 0; mt < 3; mt++)
                    mma_tf32(acc[mt][nt], af[mt][0], af[mt][1], af[mt][2], af[mt][3], b0, b1);
            }
        }
        __syncthreads();   // protect buf before next gather overwrites it
    }

    // ---- epilogue ----
#pragma unroll
    for (int mt = 0; mt < 3; mt++) {
#pragma unroll
        for (int half = 0; half < 2; half++) {
            int r = m0 + mt * 16 + grp + half * 8;
            int qi = r % 48;
            if (qi < 45) {
                int frame = fp * 2 + (r >= 48 ? 1 : 0);
                float inv = 1.f / l_s[r];
                int y = wy * WH_ + qi / 9, x = wx * WW_ + qi % 9;
                float* yp = g_y + ((size_t)(frame * H + y) * W + x) * C
                            + head * HD + nw * 32;
#pragma unroll
                for (int nt = 0; nt < 4; nt++) {
                    float o0 = tf32r(acc[mt][nt][half * 2 + 0] * inv);
                    float o1 = tf32r(acc[mt][nt][half * 2 + 1] * inv);
                    *(float2*)(yp + nt * 8 + tg * 2) = make_float2(o0, o1);
                }
            }
        }
    }
}

// ---------------------------------------------------------------------------
// Launcher
// ---------------------------------------------------------------------------
extern "C" void kernel_launch(void* const* d_in, const int* in_sizes, int n_in,
                              void* d_out, int out_size)
{
    const float* x     = (const float*)d_in[0];
    const float* masks = (const float*)d_in[1];
    const float* Wq    = (const float*)d_in[2];
    const float* bq    = (const float*)d_in[3];
    const float* Wk    = (const float*)d_in[4];
    const float* bk    = (const float*)d_in[5];
    const float* Wv    = (const float*)d_in[6];
    const float* bv    = (const float*)d_in[7];
    const float* Wp    = (const float*)d_in[8];
    const float* bp    = (const float*)d_in[9];
    const float* pw    = (const float*)d_in[10];
    const float* pb    = (const float*)d_in[11];
    float* out = (float*)d_out;

    float *q, *k, *v, *y, *xr, *px, *pk, *pv, *wq, *wk, *wv, *wp;
    cudaGetSymbolAddress((void**)&q,  g_q);
    cudaGetSymbolAddress((void**)&k,  g_k);
    cudaGetSymbolAddress((void**)&v,  g_v);
    cudaGetSymbolAddress((void**)&y,  g_y);
    cudaGetSymbolAddress((void**)&xr, g_xr);
    cudaGetSymbolAddress((void**)&px, g_px);
    cudaGetSymbolAddress((void**)&pk, g_pk);
    cudaGetSymbolAddress((void**)&pv, g_pv);
    cudaGetSymbolAddress((void**)&wq, g_wq);
    cudaGetSymbolAddress((void**)&wk, g_wk);
    cudaGetSymbolAddress((void**)&wv, g_wv);
    cudaGetSymbolAddress((void**)&wp, g_wp);

    cudaFuncSetAttribute(gemm_tf32, cudaFuncAttributeMaxDynamicSharedMemorySize, GEMM_SMEM);
    cudaFuncSetAttribute(attn_tc,   cudaFuncAttributeMaxDynamicSharedMemorySize, ATTN_SMEM);

    round_kernel<<<(TOK * C / 4 + 255) / 256, 256>>>(x, xr, TOK * C / 4);
    round_w_kernel<<<dim3((C * C / 4 + 255) / 256, 4), 256>>>(Wq, Wk, Wv, Wp);

    dim3 gBig(4, TOK / 128);
    dim3 gSm (4, (PTOK + 127) / 128);

    gemm_tf32<<<gBig, 256, GEMM_SMEM>>>(xr, wq, bq, q, TOK, 1);
    gemm_tf32<<<gBig, 256, GEMM_SMEM>>>(xr, wk, bk, k, TOK, 1);
    gemm_tf32<<<gBig, 256, GEMM_SMEM>>>(xr, wv, bv, v, TOK, 1);

    pool_kernel<<<T * P_, 256>>>(x, pw, pb);
    gemm_tf32<<<gSm, 256, GEMM_SMEM>>>(px, wk, bk, pk, PTOK, 1);
    gemm_tf32<<<gSm, 256, GEMM_SMEM>>>(px, wv, bv, pv, PTOK, 1);

    wmask_kernel<<<1, 64>>>(masks);
    init_idx_kernel<<<NWIN, 128>>>();

    attn_tc<<<dim3(NWIN, NH, 3), 256, ATTN_SMEM>>>();

    gemm_tf32<<<gBig, 256, GEMM_SMEM>>>(y, wp, bp, out, TOK, 0);
}

// round 6
// speedup vs baseline: 3.7256x; 1.0132x over previous
#include <cuda_runtime.h>
#include <cstdint>

// ---------------------------------------------------------------------------
// Problem constants
// ---------------------------------------------------------------------------
#define T      6
#define H      40
#define W      72
#define C      512
#define NH     4
#define HD     128
#define WH_    5
#define WW_    9
#define NWIN   64
#define S_     45
#define NROLL  148
#define P_     180
#define KTOT   373
#define TKEYS  (T*KTOT)   // 2238
#define TOK    (T*H*W)    // 17280
#define PTOK   (T*P_)     // 1080
#define SCALE  0.08838834764831845f

// ---------------------------------------------------------------------------
// Scratch (device globals)
// ---------------------------------------------------------------------------
__device__ float g_q [TOK * C];
__device__ float g_k [TOK * C];
__device__ float g_v [TOK * C];
__device__ float g_y [TOK * C];
__device__ float g_xr[TOK * C];
__device__ float g_px[PTOK * C];
__device__ float g_pk[PTOK * C];
__device__ float g_pv[PTOK * C];
__device__ float g_wq[C * C];
__device__ float g_wk[C * C];
__device__ float g_wv[C * C];
__device__ float g_wp[C * C];
__device__ int   g_widx[NWIN * KTOT];
__device__ int   g_wmask[NWIN];

// ---------------------------------------------------------------------------
// Helpers
// ---------------------------------------------------------------------------
__device__ __forceinline__ float tf32r(float x) {
    unsigned u;
    asm("cvt.rna.tf32.f32 %0, %1;" : "=r"(u) : "f"(x));
    return __uint_as_float(u);
}

__device__ __forceinline__ void cpasync16(uint32_t dst, const void* src) {
    asm volatile("cp.async.cg.shared.global [%0], [%1], 16;\n"
                 :: "r"(dst), "l"(src));
}

__device__ __forceinline__ void cpasync16z(uint32_t dst, const void* src, int src_sz) {
    asm volatile("cp.async.cg.shared.global [%0], [%1], 16, %2;\n"
                 :: "r"(dst), "l"(src), "r"(src_sz));
}

__device__ __forceinline__ void mma_tf32(float* c, uint32_t a0, uint32_t a1,
                                         uint32_t a2, uint32_t a3,
                                         uint32_t b0, uint32_t b1) {
    asm volatile(
        "mma.sync.aligned.m16n8k8.row.col.f32.tf32.tf32.f32 "
        "{%0,%1,%2,%3}, {%4,%5,%6,%7}, {%8,%9}, {%0,%1,%2,%3};\n"
        : "+f"(c[0]), "+f"(c[1]), "+f"(c[2]), "+f"(c[3])
        : "r"(a0), "r"(a1), "r"(a2), "r"(a3), "r"(b0), "r"(b1));
}

__device__ __forceinline__ uint32_t smem_u32(const void* p) {
    return (uint32_t)__cvta_generic_to_shared(p);
}

// ---------------------------------------------------------------------------
// Round tensors to tf32 (rna)
// ---------------------------------------------------------------------------
__global__ void round_kernel(const float* __restrict__ in,
                             float* __restrict__ out, int n4) {
    int i = blockIdx.x * blockDim.x + threadIdx.x;
    if (i < n4) {
        float4 v = ((const float4*)in)[i];
        v.x = tf32r(v.x); v.y = tf32r(v.y); v.z = tf32r(v.z); v.w = tf32r(v.w);
        ((float4*)out)[i] = v;
    }
}

__global__ void round_w_kernel(const float* __restrict__ w0, const float* __restrict__ w1,
                               const float* __restrict__ w2, const float* __restrict__ w3)
{
    const float* src[4] = {w0, w1, w2, w3};
    float* dst[4] = {g_wq, g_wk, g_wv, g_wp};
    int m = blockIdx.y;
    int i = blockIdx.x * blockDim.x + threadIdx.x;
    if (i < C * C / 4) {
        float4 v = ((const float4*)src[m])[i];
        v.x = tf32r(v.x); v.y = tf32r(v.y); v.z = tf32r(v.z); v.w = tf32r(v.w);
        ((float4*)dst[m])[i] = v;
    }
}

// ---------------------------------------------------------------------------
// tf32 GEMM (mma.sync): C[M,512] = A[M,512] @ B[512,512] + bias  (R4 proven)
// ---------------------------------------------------------------------------
#define GAS 36
#define GBS 136
#define GEMM_SMEM ((2*128*GAS + 2*32*GBS) * 4)

__global__ __launch_bounds__(256) void gemm_tf32(
    const float* __restrict__ A, const float* __restrict__ B,
    const float* __restrict__ bias, float* __restrict__ Cc, int M, int round)
{
    extern __shared__ float sm[];
    float* As = sm;
    float* Bs = sm + 2 * 128 * GAS;
    const int tid  = threadIdx.x;
    const int lane = tid & 31, warp = tid >> 5;
    const int grp  = lane >> 2, tg = lane & 3;
    const int m_base = (warp >> 2) * 64, n_base = (warp & 3) * 32;
    const int row0 = blockIdx.y * 128, col0 = blockIdx.x * 128;

    uint32_t s_as = smem_u32(As);
    uint32_t s_bs = smem_u32(Bs);

    const int arow = tid >> 1, acol = (tid & 1) * 16;
    const int brow = tid >> 3, bcol = (tid & 7) * 16;
    int agr = row0 + arow; if (agr > M - 1) agr = M - 1;
    const float* agp = A + (size_t)agr * 512 + acol;
    const float* bgp = B + (size_t)brow * 512 + col0 + bcol;
    uint32_t adst = s_as + (arow * GAS + acol) * 4;
    uint32_t bdst = s_bs + (brow * GBS + bcol) * 4;
    const uint32_t abuf = 128 * GAS * 4, bbuf = 32 * GBS * 4;

    float acc[4][4][4];
#pragma unroll
    for (int i = 0; i < 4; i++)
#pragma unroll
        for (int j = 0; j < 4; j++)
#pragma unroll
            for (int r = 0; r < 4; r++) acc[i][j][r] = 0.f;

#pragma unroll
    for (int j = 0; j < 4; j++) cpasync16(adst + j * 16, agp + j * 4);
#pragma unroll
    for (int j = 0; j < 4; j++) cpasync16(bdst + j * 16, bgp + j * 4);
    asm volatile("cp.async.commit_group;\n");

    for (int it = 0; it < 16; ++it) {
        int buf = it & 1;
        if (it < 15) {
            int k0 = (it + 1) * 32;
            uint32_t ad = adst + (buf ^ 1) * abuf;
            uint32_t bd = bdst + (buf ^ 1) * bbuf;
#pragma unroll
            for (int j = 0; j < 4; j++) cpasync16(ad + j * 16, agp + k0 + j * 4);
#pragma unroll
            for (int j = 0; j < 4; j++)
                cpasync16(bd + j * 16, bgp + (size_t)k0 * 512 + j * 4);
            asm volatile("cp.async.commit_group;\n");
            asm volatile("cp.async.wait_group 1;\n");
        } else {
            asm volatile("cp.async.wait_group 0;\n");
        }
        __syncthreads();
        const float* a_s = As + buf * 128 * GAS;
        const float* b_s = Bs + buf * 32 * GBS;
#pragma unroll
        for (int k8 = 0; k8 < 4; k8++) {
            uint32_t af[4][4];
#pragma unroll
            for (int mt = 0; mt < 4; mt++) {
                const float* p = a_s + (m_base + mt * 16 + grp) * GAS + k8 * 8 + tg;
                af[mt][0] = __float_as_uint(p[0]);
                af[mt][1] = __float_as_uint(p[8 * GAS]);
                af[mt][2] = __float_as_uint(p[4]);
                af[mt][3] = __float_as_uint(p[8 * GAS + 4]);
            }
#pragma unroll
            for (int nt = 0; nt < 4; nt++) {
                const float* p = b_s + (k8 * 8 + tg) * GBS + n_base + nt * 8 + grp;
                uint32_t b0 = __float_as_uint(p[0]);
                uint32_t b1 = __float_as_uint(p[4 * GBS]);
#pragma unroll
                for (int mt = 0; mt < 4; mt++)
                    mma_tf32(acc[mt][nt], af[mt][0], af[mt][1], af[mt][2], af[mt][3], b0, b1);
            }
        }
        __syncthreads();
    }

#pragma unroll
    for (int mt = 0; mt < 4; mt++) {
        int r0 = row0 + m_base + mt * 16 + grp;
#pragma unroll
        for (int nt = 0; nt < 4; nt++) {
            int cc = col0 + n_base + nt * 8 + tg * 2;
            float b0v = bias[cc], b1v = bias[cc + 1];
            float o0 = acc[mt][nt][0] + b0v, o1 = acc[mt][nt][1] + b1v;
            float o2 = acc[mt][nt][2] + b0v, o3 = acc[mt][nt][3] + b1v;
            if (round) { o0 = tf32r(o0); o1 = tf32r(o1); o2 = tf32r(o2); o3 = tf32r(o3); }
            if (r0 < M)     *(float2*)(Cc + (size_t)r0 * 512 + cc)       = make_float2(o0, o1);
            if (r0 + 8 < M) *(float2*)(Cc + (size_t)(r0 + 8) * 512 + cc) = make_float2(o2, o3);
        }
    }
}

// ---------------------------------------------------------------------------
// Depthwise 4x4/stride-4 pool conv -> tf32-rounded px
// ---------------------------------------------------------------------------
__global__ void pool_kernel(const float* __restrict__ x,
                            const float* __restrict__ pw,
                            const float* __restrict__ pb)
{
    int o = blockIdx.x;
    int f = o / 180, r = o % 180;
    int py = r / 18, pxx = r % 18;
    for (int c = threadIdx.x; c < C; c += blockDim.x) {
        float s = pb[c];
#pragma unroll
        for (int i = 0; i < 4; i++)
#pragma unroll
            for (int j = 0; j < 4; j++)
                s += x[((size_t)(f * H + py * 4 + i) * W + (pxx * 4 + j)) * C + c]
                     * pw[(i * 4 + j) * C + c];
        g_px[(size_t)o * C + c] = tf32r(s);
    }
}

// ---------------------------------------------------------------------------
// Window mask + key index table
// ---------------------------------------------------------------------------
__global__ void wmask_kernel(const float* __restrict__ masks)
{
    int win = threadIdx.x;
    if (win >= NWIN) return;
    int wy = win >> 3, wx = win & 7;
    float s = 0.f;
    for (int f = 0; f < T; f++)
        for (int i = 0; i < WH_; i++)
            for (int j = 0; j < WW_; j++)
                s += masks[(size_t)(f * H + wy * WH_ + i) * W + (wx * WW_ + j)];
    g_wmask[win] = (s > 0.f) ? 1 : 0;
}

__global__ void init_idx_kernel()
{
    __shared__ int vind[NROLL];
    if (threadIdx.x == 0) {
        int cnt = 0;
        for (int s = 0; s < 4; s++)
            for (int i = 0; i < WH_; i++)
                for (int j = 0; j < WW_; j++) {
                    bool inval;
                    if (s == 0)      inval = (i < 2 && j < 4);
                    else if (s == 1) inval = (i < 2 && j >= 5);
                    else if (s == 2) inval = (i >= 3 && j < 4);
                    else             inval = (i >= 3 && j >= 5);
                    if (!inval) vind[cnt++] = s * 45 + i * 9 + j;
                }
    }
    __syncthreads();
    int win = blockIdx.x;
    int wy = win >> 3, wx = win & 7;
    for (int j = threadIdx.x; j < KTOT; j += blockDim.x) {
        int val;
        if (j < S_) {
            int i = j / 9, jj = j % 9;
            val = (wy * WH_ + i) * W + (wx * WW_ + jj);
        } else if (j < S_ + NROLL) {
            int v = vind[j - S_];
            int s = v / 45, pos = v % 45;
            int i = pos / 9, jj = pos % 9;
            int s0 = (s < 2) ? -3 : 3;
            int s1 = ((s & 1) == 0) ? -5 : 5;
            int y = wy * WH_ + i, x = wx * WW_ + jj;
            int yy = ((y - s0) % H + H) % H;
            int xx = ((x - s1) % W + W) % W;
            val = yy * W + xx;
        } else {
            val = -(j - (S_ + NROLL)) - 1;
        }
        g_widx[win * KTOT + j] = val;
    }
}

// ---------------------------------------------------------------------------
// Attention v4: block=(win, head, frame-pair), 256 thr / 8 warps, 2 blocks/SM.
// Q fragment-packed (LDS.128 A-frags), KC=32 single-buffered K/V gather.
// smem: q_f 48K + K 16.5K + V 17K + P 13.5K = 95K -> occupancy 2.
// ---------------------------------------------------------------------------
#define KS 132
#define VS 136
#define PS 36
#define KC 32
#define QF_FLOATS (6*16*32*4)                  // 12288
#define ATTN_SMEM ((QF_FLOATS + KC*KS + KC*VS + 96*PS) * 4)

__global__ __launch_bounds__(256, 2) void attn_tc()
{
    const int win = blockIdx.x, head = blockIdx.y, fp = blockIdx.z;
    const int tid  = threadIdx.x;
    const int lane = tid & 31, warp = tid >> 5;
    const int grp  = lane >> 2, tg = lane & 3;
    const int m0   = (warp >> 2) * 48;         // 0 or 48
    const int mtb  = (warp >> 2) * 3;          // base m16-tile: 0 or 3
    const int nw   = warp & 3;                 // 0..3
    extern __shared__ float sm[];
    float* q_f = sm;                           // [6][16][32] float4
    float* k_s = q_f + QF_FLOATS;              // [32][132]
    float* v_s = k_s + KC * KS;                // [32][136]
    float* p_s = v_s + KC * VS;                // [96][36]
    __shared__ float m_s[96], l_s[96], corr_s[96];

    const int wy = win >> 3, wx = win & 7;
    const int masked = g_wmask[win];
    const int nch    = masked ? (TKEYS + KC - 1) / KC : 4;   // 70 or 4
    const int* widx  = g_widx + win * KTOT;

    // ---- load Q into fragment-packed layout ----
    // q_f[((mt*16 + k8)*32 + lane)*4 + comp], comp = hi + 2*cq
    for (int idx = tid; idx < 96 * 32; idx += 256) {
        int row = idx >> 5, q4 = idx & 31;
        int qi = row % 48;
        int frame = fp * 2 + (row >= 48 ? 1 : 0);
        float4 v = make_float4(0.f, 0.f, 0.f, 0.f);
        if (qi < 45) {
            int y = wy * WH_ + qi / 9, x = wx * WW_ + qi % 9;
            v = *(const float4*)(g_q + ((size_t)(frame * H + y) * W + x) * C
                                 + head * HD + q4 * 4);
        }
        int mt = row >> 4, rr = row & 15;
        int rg = rr & 7, hi = rr >> 3;
        int k8 = q4 >> 1, cq = q4 & 1;
        int comp = hi + 2 * cq;
        float* base = q_f + ((mt * 16 + k8) * 32 + rg * 4) * 4 + comp;
        base[0]  = v.x;   // tg=0
        base[4]  = v.y;   // tg=1
        base[8]  = v.z;   // tg=2
        base[12] = v.w;   // tg=3
    }
    if (tid < 96) { m_s[tid] = -1e30f; l_s[tid] = 0.f; corr_s[tid] = 1.f; }

    float acc[3][4][4];
#pragma unroll
    for (int i = 0; i < 3; i++)
#pragma unroll
        for (int j = 0; j < 4; j++)
#pragma unroll
            for (int r = 0; r < 4; r++) acc[i][j][r] = 0.f;

    // ---- gather chunk cc into the single K/V buffer ----
    auto gather = [&](int cc) {
        uint32_t kb_s = smem_u32(k_s);
        uint32_t vb_s = smem_u32(v_s);
        int q4 = tid & 31;
#pragma unroll
        for (int i = 0; i < 4; i++) {
            int key = i * 8 + (tid >> 5);
            const float *ksrc = g_k, *vsrc = g_k;
            int sz = 0;
            bool valid;
            int f2, j;
            if (masked) {
                int g = cc * KC + key;
                valid = (g < TKEYS);
                f2 = g / KTOT; j = g - f2 * KTOT;
            } else {
                j = (cc & 1) * 32 + key;
                valid = (j < S_);
                f2 = fp * 2 + (cc >> 1);
            }
            if (valid) {
                int id = widx[j];
                size_t off;
                if (id >= 0) {
                    off = ((size_t)(f2 * (H * W) + id)) * C + head * HD + q4 * 4;
                    ksrc = g_k + off; vsrc = g_v + off;
                } else {
                    off = ((size_t)(f2 * P_ + (-id - 1))) * C + head * HD + q4 * 4;
                    ksrc = g_pk + off; vsrc = g_pv + off;
                }
                sz = 16;
            }
            cpasync16z(kb_s + (key * KS + q4 * 4) * 4, ksrc, sz);
            cpasync16z(vb_s + (key * VS + q4 * 4) * 4, vsrc, sz);
        }
        asm volatile("cp.async.commit_group;\n");
    };

    gather(0);

    for (int cc = 0; cc < nch; cc++) {
        asm volatile("cp.async.wait_group 0;\n");
        __syncthreads();   // K/V chunk + (first iter) Q tile visible

        const int rem = masked ? min(KC, TKEYS - cc * KC)
                               : ((cc & 1) ? (S_ - 32) : 32);

        // ---- QK^T: 96 x 32, warp covers cols [nw*8, nw*8+8) ----
        {
            float c[3][4];
#pragma unroll
            for (int mt = 0; mt < 3; mt++)
#pragma unroll
                for (int r = 0; r < 4; r++) c[mt][r] = 0.f;
#pragma unroll
            for (int k8 = 0; k8 < 16; k8++) {
                uint32_t af[3][4];
#pragma unroll
                for (int mt = 0; mt < 3; mt++) {
                    float4 a = *(const float4*)(q_f + (((mtb + mt) * 16 + k8) * 32 + lane) * 4);
                    af[mt][0] = __float_as_uint(a.x);
                    af[mt][1] = __float_as_uint(a.y);
                    af[mt][2] = __float_as_uint(a.z);
                    af[mt][3] = __float_as_uint(a.w);
                }
                const float* p = k_s + (nw * 8 + grp) * KS + k8 * 8 + tg;
                uint32_t b0 = __float_as_uint(p[0]);
                uint32_t b1 = __float_as_uint(p[4]);
#pragma unroll
                for (int mt = 0; mt < 3; mt++)
                    mma_tf32(c[mt], af[mt][0], af[mt][1], af[mt][2], af[mt][3], b0, b1);
            }
#pragma unroll
            for (int mt = 0; mt < 3; mt++) {
                int r0 = m0 + mt * 16 + grp, col = nw * 8 + tg * 2;
                *(float2*)&p_s[r0 * PS + col]       = make_float2(c[mt][0], c[mt][1]);
                *(float2*)&p_s[(r0 + 8) * PS + col] = make_float2(c[mt][2], c[mt][3]);
            }
        }
        __syncthreads();

        // ---- online softmax (192 threads, 2 per row, 16 cols each) ----
        if (tid < 192) {
            int row = tid >> 1, half = tid & 1;
            bool rowok = masked || ((row >= 48 ? 1 : 0) == (cc >> 1));
            float* pr = p_s + row * PS + half * 16;
            int cbase = half * 16;
            float mold = m_s[row], cm = mold;
#pragma unroll
            for (int j = 0; j < 16; j++) {
                float s = (rowok && cbase + j < rem) ? pr[j] * SCALE : -1e30f;
                cm = fmaxf(cm, s);
            }
            cm = fmaxf(cm, __shfl_xor_sync(0xffffffffu, cm, 1));
            float corr = __expf(mold - cm);
            float sum = 0.f;
#pragma unroll
            for (int j = 0; j < 16; j++) {
                float e = (rowok && cbase + j < rem) ? __expf(pr[j] * SCALE - cm) : 0.f;
                sum += e;
                pr[j] = tf32r(e);
            }
            sum += __shfl_xor_sync(0xffffffffu, sum, 1);
            if (half == 0) {
                m_s[row] = cm;
                l_s[row] = l_s[row] * corr + sum;
                corr_s[row] = corr;
            }
        }
        __syncthreads();

        // ---- rescale acc + P @ V (warp covers d [nw*32, +32)) ----
#pragma unroll
        for (int mt = 0; mt < 3; mt++) {
            float cr0 = corr_s[m0 + mt * 16 + grp], cr1 = corr_s[m0 + mt * 16 + grp + 8];
#pragma unroll
            for (int nt = 0; nt < 4; nt++) {
                acc[mt][nt][0] *= cr0; acc[mt][nt][1] *= cr0;
                acc[mt][nt][2] *= cr1; acc[mt][nt][3] *= cr1;
            }
        }
#pragma unroll
        for (int k8 = 0; k8 < 4; k8++) {
            int kk = k8 * 8;
            uint32_t af[3][4];
#pragma unroll
            for (int mt = 0; mt < 3; mt++) {
                const float* p = p_s + (m0 + mt * 16 + grp) * PS + kk + tg;
                af[mt][0] = __float_as_uint(p[0]);
                af[mt][1] = __float_as_uint(p[8 * PS]);
                af[mt][2] = __float_as_uint(p[4]);
                af[mt][3] = __float_as_uint(p[8 * PS + 4]);
            }
#pragma unroll
            for (int nt = 0; nt < 4; nt++) {
                const float* p = v_s + (kk + tg) * VS + nw * 32 + nt * 8 + grp;
                uint32_t b0 = __float_as_uint(p[0]);
                uint32_t b1 = __float_as_uint(p[4 * VS]);
#pragma unroll
                for (int mt = 0; mt < 3; mt++)
                    mma_tf32(acc[mt][nt], af[mt][0], af[mt][1], af[mt][2], af[mt][3], b0, b1);
            }
        }
        __syncthreads();   // K/V consumed -> safe to overwrite

        if (cc + 1 < nch) gather(cc + 1);
    }

    // ---- epilogue ----
#pragma unroll
    for (int mt = 0; mt < 3; mt++) {
#pragma unroll
        for (int half = 0; half < 2; half++) {
            int r = m0 + mt * 16 + grp + half * 8;
            int qi = r % 48;
            if (qi < 45) {
                int frame = fp * 2 + (r >= 48 ? 1 : 0);
                float inv = 1.f / l_s[r];
                int y = wy * WH_ + qi / 9, x = wx * WW_ + qi % 9;
                float* yp = g_y + ((size_t)(frame * H + y) * W + x) * C
                            + head * HD + nw * 32;
#pragma unroll
                for (int nt = 0; nt < 4; nt++) {
                    float o0 = tf32r(acc[mt][nt][half * 2 + 0] * inv);
                    float o1 = tf32r(acc[mt][nt][half * 2 + 1] * inv);
                    *(float2*)(yp + nt * 8 + tg * 2) = make_float2(o0, o1);
                }
            }
        }
    }
}

// ---------------------------------------------------------------------------
// Launcher
// ---------------------------------------------------------------------------
extern "C" void kernel_launch(void* const* d_in, const int* in_sizes, int n_in,
                              void* d_out, int out_size)
{
    const float* x     = (const float*)d_in[0];
    const float* masks = (const float*)d_in[1];
    const float* Wq    = (const float*)d_in[2];
    const float* bq    = (const float*)d_in[3];
    const float* Wk    = (const float*)d_in[4];
    const float* bk    = (const float*)d_in[5];
    const float* Wv    = (const float*)d_in[6];
    const float* bv    = (const float*)d_in[7];
    const float* Wp    = (const float*)d_in[8];
    const float* bp    = (const float*)d_in[9];
    const float* pw    = (const float*)d_in[10];
    const float* pb    = (const float*)d_in[11];
    float* out = (float*)d_out;

    float *q, *k, *v, *y, *xr, *px, *pk, *pv, *wq, *wk, *wv, *wp;
    cudaGetSymbolAddress((void**)&q,  g_q);
    cudaGetSymbolAddress((void**)&k,  g_k);
    cudaGetSymbolAddress((void**)&v,  g_v);
    cudaGetSymbolAddress((void**)&y,  g_y);
    cudaGetSymbolAddress((void**)&xr, g_xr);
    cudaGetSymbolAddress((void**)&px, g_px);
    cudaGetSymbolAddress((void**)&pk, g_pk);
    cudaGetSymbolAddress((void**)&pv, g_pv);
    cudaGetSymbolAddress((void**)&wq, g_wq);
    cudaGetSymbolAddress((void**)&wk, g_wk);
    cudaGetSymbolAddress((void**)&wv, g_wv);
    cudaGetSymbolAddress((void**)&wp, g_wp);

    cudaFuncSetAttribute(gemm_tf32, cudaFuncAttributeMaxDynamicSharedMemorySize, GEMM_SMEM);
    cudaFuncSetAttribute(attn_tc,   cudaFuncAttributeMaxDynamicSharedMemorySize, ATTN_SMEM);

    round_kernel<<<(TOK * C / 4 + 255) / 256, 256>>>(x, xr, TOK * C / 4);
    round_w_kernel<<<dim3((C * C / 4 + 255) / 256, 4), 256>>>(Wq, Wk, Wv, Wp);

    dim3 gBig(4, TOK / 128);                 // (4, 135)
    dim3 gSm (4, (PTOK + 127) / 128);        // (4, 9)

    gemm_tf32<<<gBig, 256, GEMM_SMEM>>>(xr, wq, bq, q, TOK, 1);
    gemm_tf32<<<gBig, 256, GEMM_SMEM>>>(xr, wk, bk, k, TOK, 1);
    gemm_tf32<<<gBig, 256, GEMM_SMEM>>>(xr, wv, bv, v, TOK, 1);

    pool_kernel<<<T * P_, 256>>>(x, pw, pb);
    gemm_tf32<<<gSm, 256, GEMM_SMEM>>>(px, wk, bk, pk, PTOK, 1);
    gemm_tf32<<<gSm, 256, GEMM_SMEM>>>(px, wv, bv, pv, PTOK, 1);

    wmask_kernel<<<1, 64>>>(masks);
    init_idx_kernel<<<NWIN, 128>>>();

    attn_tc<<<dim3(NWIN, NH, 3), 256, ATTN_SMEM>>>();

    gemm_tf32<<<gBig, 256, GEMM_SMEM>>>(y, wp, bp, out, TOK, 0);
}

// round 7
// speedup vs baseline: 5.8344x; 1.5660x over previous
#include <cuda_runtime.h>
#include <cuda_fp16.h>
#include <cstdint>

// ---------------------------------------------------------------------------
// Problem constants
// ---------------------------------------------------------------------------
#define T      6
#define H      40
#define W      72
#define C      512
#define NH     4
#define HD     128
#define WH_    5
#define WW_    9
#define NWIN   64
#define S_     45
#define NROLL  148
#define P_     180
#define KTOT   373
#define TKEYS  (T*KTOT)   // 2238
#define TOK    (T*H*W)    // 17280
#define PTOK   (T*P_)     // 1080
#define SCALE  0.08838834764831845f

// ---------------------------------------------------------------------------
// Scratch (device globals) — fp16 operand tensors
// ---------------------------------------------------------------------------
__device__ __half g_xh[TOK * C];
__device__ __half g_qh[TOK * C];
__device__ __half g_kh[TOK * C];
__device__ __half g_vh[TOK * C];
__device__ __half g_yh[TOK * C];
__device__ __half g_pxh[PTOK * C];
__device__ __half g_pkh[PTOK * C];
__device__ __half g_pvh[PTOK * C];
__device__ __half g_wqh[C * C];   // W^T as half: [n][k]
__device__ __half g_wkh[C * C];
__device__ __half g_wvh[C * C];
__device__ __half g_wph[C * C];
__device__ int    g_widx[NWIN * KTOT];
__device__ int    g_wmask[NWIN];

// ---------------------------------------------------------------------------
// Helpers
// ---------------------------------------------------------------------------
__device__ __forceinline__ void cpasync16(uint32_t dst, const void* src) {
    asm volatile("cp.async.cg.shared.global [%0], [%1], 16;\n"
                 :: "r"(dst), "l"(src));
}

__device__ __forceinline__ void cpasync16z(uint32_t dst, const void* src, int src_sz) {
    asm volatile("cp.async.cg.shared.global [%0], [%1], 16, %2;\n"
                 :: "r"(dst), "l"(src), "r"(src_sz));
}

__device__ __forceinline__ void mma_f16(float* c, uint32_t a0, uint32_t a1,
                                        uint32_t a2, uint32_t a3,
                                        uint32_t b0, uint32_t b1) {
    asm volatile(
        "mma.sync.aligned.m16n8k16.row.col.f32.f16.f16.f32 "
        "{%0,%1,%2,%3}, {%4,%5,%6,%7}, {%8,%9}, {%0,%1,%2,%3};\n"
        : "+f"(c[0]), "+f"(c[1]), "+f"(c[2]), "+f"(c[3])
        : "r"(a0), "r"(a1), "r"(a2), "r"(a3), "r"(b0), "r"(b1));
}

__device__ __forceinline__ void ldmatrix_x2_trans(uint32_t& r0, uint32_t& r1,
                                                  uint32_t addr) {
    asm volatile("ldmatrix.sync.aligned.m8n8.x2.trans.shared.b16 {%0,%1}, [%2];"
                 : "=r"(r0), "=r"(r1) : "r"(addr));
}

__device__ __forceinline__ uint32_t smem_u32(const void* p) {
    return (uint32_t)__cvta_generic_to_shared(p);
}

__device__ __forceinline__ uint32_t h2u(float a, float b) {
    __half2 h = __floats2half2_rn(a, b);
    return *(uint32_t*)&h;
}

// ---------------------------------------------------------------------------
// Conversions
// ---------------------------------------------------------------------------
__global__ void conv_x_kernel(const float* __restrict__ in,
                              __half* __restrict__ out, int n4) {
    int i = blockIdx.x * blockDim.x + threadIdx.x;
    if (i < n4) {
        float4 v = ((const float4*)in)[i];
        ((uint32_t*)out)[i * 2 + 0] = h2u(v.x, v.y);
        ((uint32_t*)out)[i * 2 + 1] = h2u(v.z, v.w);
    }
}

// transpose + convert all 4 weight matrices: dst[n][k] = half(W[k][n])
__global__ void conv_wT_kernel(const float* __restrict__ w0, const float* __restrict__ w1,
                               const float* __restrict__ w2, const float* __restrict__ w3)
{
    __shared__ float t[32][33];
    const float* src[4] = {w0, w1, w2, w3};
    __half* dst[4] = {g_wqh, g_wkh, g_wvh, g_wph};
    int m = blockIdx.z;
    int bx = blockIdx.x * 32, by = blockIdx.y * 32;
    int tx = threadIdx.x & 31, ty0 = threadIdx.x >> 5;
#pragma unroll
    for (int i = 0; i < 4; i++) {
        int ty = ty0 + i * 8;
        t[ty][tx] = src[m][(size_t)(by + ty) * C + bx + tx];
    }
    __syncthreads();
#pragma unroll
    for (int i = 0; i < 4; i++) {
        int ty = ty0 + i * 8;
        dst[m][(size_t)(bx + ty) * C + by + tx] = __float2half_rn(t[tx][ty]);
    }
}

// ---------------------------------------------------------------------------
// fp16 GEMM: C[M,512] = A[M,512] @ W[512,512] + bias
//   A half [m][k], Bt = W^T half [n][k]. 128x128 tile, k-tile 64, 8 iters.
//   smem rows padded to 72 halfs (stride 36 words -> conflict-free frags).
// ---------------------------------------------------------------------------
#define GH_ROW   72
#define GH_TILEB (128 * GH_ROW * 2)     // 18432 bytes
#define GH_SMEM  (4 * GH_TILEB)         // A x2 + B x2 = 73728

__global__ __launch_bounds__(256, 2) void gemm_h(
    const __half* __restrict__ A, const __half* __restrict__ Bt,
    const float* __restrict__ bias, __half* __restrict__ Ch,
    float* __restrict__ Cf, int M, int write_half)
{
    extern __shared__ char smc[];
    __half* a_sm = (__half*)smc;                       // [2][128][72]
    __half* b_sm = (__half*)(smc + 2 * GH_TILEB);      // [2][128][72]
    const int tid  = threadIdx.x;
    const int lane = tid & 31, warp = tid >> 5;
    const int grp  = lane >> 2, tg = lane & 3;
    const int mb = (warp >> 2) * 64, nb = (warp & 3) * 32;
    const int row0 = blockIdx.y * 128, col0 = blockIdx.x * 128;

    const uint32_t sA = smem_u32(a_sm);
    const uint32_t sB = smem_u32(b_sm);

    float acc[4][4][4];
#pragma unroll
    for (int i = 0; i < 4; i++)
#pragma unroll
        for (int j = 0; j < 4; j++)
#pragma unroll
            for (int r = 0; r < 4; r++) acc[i][j][r] = 0.f;

    auto load_tile = [&](int kt, int b) {
#pragma unroll
        for (int i = 0; i < 4; i++) {
            int idx = i * 256 + tid;
            int r = idx >> 3, seg = idx & 7;
            int gr = row0 + r; if (gr > M - 1) gr = M - 1;
            cpasync16(sA + b * GH_TILEB + r * (GH_ROW * 2) + seg * 16,
                      A + (size_t)gr * 512 + kt * 64 + seg * 8);
        }
#pragma unroll
        for (int i = 0; i < 4; i++) {
            int idx = i * 256 + tid;
            int r = idx >> 3, seg = idx & 7;
            cpasync16(sB + b * GH_TILEB + r * (GH_ROW * 2) + seg * 16,
                      Bt + (size_t)(col0 + r) * 512 + kt * 64 + seg * 8);
        }
        asm volatile("cp.async.commit_group;\n");
    };

    load_tile(0, 0);

    for (int it = 0; it < 8; it++) {
        if (it < 7) {
            load_tile(it + 1, (it & 1) ^ 1);
            asm volatile("cp.async.wait_group 1;\n");
        } else {
            asm volatile("cp.async.wait_group 0;\n");
        }
        __syncthreads();
        const __half* at = a_sm + (it & 1) * 128 * GH_ROW;
        const __half* bt = b_sm + (it & 1) * 128 * GH_ROW;
#pragma unroll
        for (int s = 0; s < 4; s++) {
            uint32_t af[4][4];
#pragma unroll
            for (int mt = 0; mt < 4; mt++) {
                const __half* p = at + (mb + mt * 16 + grp) * GH_ROW + s * 16 + tg * 2;
                af[mt][0] = *(const uint32_t*)p;
                af[mt][1] = *(const uint32_t*)(p + 8 * GH_ROW);
                af[mt][2] = *(const uint32_t*)(p + 8);
                af[mt][3] = *(const uint32_t*)(p + 8 * GH_ROW + 8);
            }
#pragma unroll
            for (int nt = 0; nt < 4; nt++) {
                const __half* pb = bt + (nb + nt * 8 + grp) * GH_ROW + s * 16 + tg * 2;
                uint32_t b0 = *(const uint32_t*)pb;
                uint32_t b1 = *(const uint32_t*)(pb + 8);
#pragma unroll
                for (int mt = 0; mt < 4; mt++)
                    mma_f16(acc[mt][nt], af[mt][0], af[mt][1], af[mt][2], af[mt][3], b0, b1);
            }
        }
        __syncthreads();
    }

#pragma unroll
    for (int mt = 0; mt < 4; mt++) {
        int r0 = row0 + mb + mt * 16 + grp;
#pragma unroll
        for (int nt = 0; nt < 4; nt++) {
            int cc = col0 + nb + nt * 8 + tg * 2;
            float b0v = bias[cc], b1v = bias[cc + 1];
            float o0 = acc[mt][nt][0] + b0v, o1 = acc[mt][nt][1] + b1v;
            float o2 = acc[mt][nt][2] + b0v, o3 = acc[mt][nt][3] + b1v;
            if (write_half) {
                if (r0 < M)     *(uint32_t*)&Ch[(size_t)r0 * 512 + cc]       = h2u(o0, o1);
                if (r0 + 8 < M) *(uint32_t*)&Ch[(size_t)(r0 + 8) * 512 + cc] = h2u(o2, o3);
            } else {
                if (r0 < M)     *(float2*)(Cf + (size_t)r0 * 512 + cc)       = make_float2(o0, o1);
                if (r0 + 8 < M) *(float2*)(Cf + (size_t)(r0 + 8) * 512 + cc) = make_float2(o2, o3);
            }
        }
    }
}

// ---------------------------------------------------------------------------
// Depthwise 4x4/stride-4 pool conv -> half px
// ---------------------------------------------------------------------------
__global__ void pool_kernel(const float* __restrict__ x,
                            const float* __restrict__ pw,
                            const float* __restrict__ pb)
{
    int o = blockIdx.x;
    int f = o / 180, r = o % 180;
    int py = r / 18, pxx = r % 18;
    for (int c = threadIdx.x; c < C; c += blockDim.x) {
        float s = pb[c];
#pragma unroll
        for (int i = 0; i < 4; i++)
#pragma unroll
            for (int j = 0; j < 4; j++)
                s += x[((size_t)(f * H + py * 4 + i) * W + (pxx * 4 + j)) * C + c]
                     * pw[(i * 4 + j) * C + c];
        g_pxh[(size_t)o * C + c] = __float2half_rn(s);
    }
}

// ---------------------------------------------------------------------------
// Window mask + key index table
// ---------------------------------------------------------------------------
__global__ void wmask_kernel(const float* __restrict__ masks)
{
    int win = threadIdx.x;
    if (win >= NWIN) return;
    int wy = win >> 3, wx = win & 7;
    float s = 0.f;
    for (int f = 0; f < T; f++)
        for (int i = 0; i < WH_; i++)
            for (int j = 0; j < WW_; j++)
                s += masks[(size_t)(f * H + wy * WH_ + i) * W + (wx * WW_ + j)];
    g_wmask[win] = (s > 0.f) ? 1 : 0;
}

__global__ void init_idx_kernel()
{
    __shared__ int vind[NROLL];
    if (threadIdx.x == 0) {
        int cnt = 0;
        for (int s = 0; s < 4; s++)
            for (int i = 0; i < WH_; i++)
                for (int j = 0; j < WW_; j++) {
                    bool inval;
                    if (s == 0)      inval = (i < 2 && j < 4);
                    else if (s == 1) inval = (i < 2 && j >= 5);
                    else if (s == 2) inval = (i >= 3 && j < 4);
                    else             inval = (i >= 3 && j >= 5);
                    if (!inval) vind[cnt++] = s * 45 + i * 9 + j;
                }
    }
    __syncthreads();
    int win = blockIdx.x;
    int wy = win >> 3, wx = win & 7;
    for (int j = threadIdx.x; j < KTOT; j += blockDim.x) {
        int val;
        if (j < S_) {
            int i = j / 9, jj = j % 9;
            val = (wy * WH_ + i) * W + (wx * WW_ + jj);
        } else if (j < S_ + NROLL) {
            int v = vind[j - S_];
            int s = v / 45, pos = v % 45;
            int i = pos / 9, jj = pos % 9;
            int s0 = (s < 2) ? -3 : 3;
            int s1 = ((s & 1) == 0) ? -5 : 5;
            int y = wy * WH_ + i, x = wx * WW_ + jj;
            int yy = ((y - s0) % H + H) % H;
            int xx = ((x - s1) % W + W) % W;
            val = yy * W + xx;
        } else {
            val = -(j - (S_ + NROLL)) - 1;
        }
        g_widx[win * KTOT + j] = val;
    }
}

// ---------------------------------------------------------------------------
// Attention fp16: block=(win, head, frame-pair), 256 thr / 8 warps.
// Q fragment-packed (uint4/LDS.128 A-frags), KC=32 K/V, scores fp32,
// probs half, V B-frags via ldmatrix.x2.trans.
// smem: q_f 24K + K 8.5K + V 8.5K + sc 13.5K + ph 7.5K = 62K.
// ---------------------------------------------------------------------------
#define KVS  136                 // K/V smem row stride in halfs
#define SCS  36                  // score row stride (floats)
#define PHS  40                  // prob row stride (halfs)
#define KC   32
#define OFF_K   24576
#define OFF_V   (OFF_K + 8704)
#define OFF_SC  (OFF_V + 8704)
#define OFF_PH  (OFF_SC + 13824)
#define ATTN_SMEM (OFF_PH + 7680)   // 63488

__global__ __launch_bounds__(256, 2) void attn_h()
{
    const int win = blockIdx.x, head = blockIdx.y, fp = blockIdx.z;
    const int tid  = threadIdx.x;
    const int lane = tid & 31, warp = tid >> 5;
    const int grp  = lane >> 2, tg = lane & 3;
    const int m0   = (warp >> 2) * 48;         // row offset: 0 or 48
    const int mtb  = (warp >> 2) * 3;          // m16 tile base: 0 or 3
    const int nw   = warp & 3;                 // 0..3
    extern __shared__ char smc[];
    uint32_t* qf  = (uint32_t*)smc;            // [6 mt][8 s][32 lane][4] u32
    __half*   k_s = (__half*)(smc + OFF_K);    // [32][136]
    __half*   v_s = (__half*)(smc + OFF_V);    // [32][136]
    float*    sc  = (float*)(smc + OFF_SC);    // [96][36]
    __half*   ph  = (__half*)(smc + OFF_PH);   // [96][40]
    __shared__ float m_s[96], l_s[96], corr_s[96];

    const int wy = win >> 3, wx = win & 7;
    const int masked = g_wmask[win];
    const int nch    = masked ? (TKEYS + KC - 1) / KC : 4;   // 70 or 4
    const int* widx  = g_widx + win * KTOT;

    // ---- load Q into fragment-packed layout ----
    for (int idx = tid; idx < 96 * 16; idx += 256) {
        int row = idx >> 4, seg8 = idx & 15;     // seg8: 8-half segment
        int qi = row % 48;
        int frame = fp * 2 + (row >= 48 ? 1 : 0);
        uint4 v = make_uint4(0u, 0u, 0u, 0u);
        if (qi < 45) {
            int y = wy * WH_ + qi / 9, x = wx * WW_ + qi % 9;
            v = *(const uint4*)(g_qh + ((size_t)(frame * H + y) * W + x) * C
                                + head * HD + seg8 * 8);
        }
        int mt = row >> 4, rr = row & 15;
        int rg = rr & 7, hi = rr >> 3;
        int s = seg8 >> 1, lo8 = seg8 & 1;
        int comp = hi + 2 * lo8;
        uint32_t* base = qf + ((mt * 8 + s) * 32 + rg * 4) * 4 + comp;
        base[0]  = v.x;   // tg 0
        base[4]  = v.y;   // tg 1
        base[8]  = v.z;   // tg 2
        base[12] = v.w;   // tg 3
    }
    if (tid < 96) { m_s[tid] = -1e30f; l_s[tid] = 0.f; corr_s[tid] = 1.f; }

    float acc[3][4][4];
#pragma unroll
    for (int i = 0; i < 3; i++)
#pragma unroll
        for (int j = 0; j < 4; j++)
#pragma unroll
            for (int r = 0; r < 4; r++) acc[i][j][r] = 0.f;

    const uint32_t kb_s = smem_u32(k_s);
    const uint32_t vb_s = smem_u32(v_s);

    // ---- gather chunk cc into K/V buffer (32 keys x 128 halfs) ----
    auto gather = [&](int cc) {
#pragma unroll
        for (int i = 0; i < 2; i++) {
            int idx = i * 256 + tid;
            int key = idx >> 4, seg = idx & 15;
            const __half *ksrc = g_kh, *vsrc = g_kh;
            int sz = 0;
            bool valid;
            int f2, j;
            if (masked) {
                int g = cc * KC + key;
                valid = (g < TKEYS);
                f2 = g / KTOT; j = g - f2 * KTOT;
            } else {
                j = (cc & 1) * 32 + key;
                valid = (j < S_);
                f2 = fp * 2 + (cc >> 1);
            }
            if (valid) {
                int id = widx[j];
                size_t off;
                if (id >= 0) {
                    off = ((size_t)(f2 * (H * W) + id)) * C + head * HD + seg * 8;
                    ksrc = g_kh + off; vsrc = g_vh + off;
                } else {
                    off = ((size_t)(f2 * P_ + (-id - 1))) * C + head * HD + seg * 8;
                    ksrc = g_pkh + off; vsrc = g_pvh + off;
                }
                sz = 16;
            }
            cpasync16z(kb_s + key * (KVS * 2) + seg * 16, ksrc, sz);
            cpasync16z(vb_s + key * (KVS * 2) + seg * 16, vsrc, sz);
        }
        asm volatile("cp.async.commit_group;\n");
    };

    gather(0);

    for (int cc = 0; cc < nch; cc++) {
        asm volatile("cp.async.wait_group 0;\n");
        __syncthreads();

        const int rem = masked ? min(KC, TKEYS - cc * KC)
                               : ((cc & 1) ? (S_ - 32) : 32);

        // ---- QK^T: 96 x 32; warp covers keys [nw*8, nw*8+8) ----
        {
            float c[3][4];
#pragma unroll
            for (int mt = 0; mt < 3; mt++)
#pragma unroll
                for (int r = 0; r < 4; r++) c[mt][r] = 0.f;
#pragma unroll
            for (int s = 0; s < 8; s++) {
                uint4 av[3];
#pragma unroll
                for (int mt = 0; mt < 3; mt++)
                    av[mt] = ((const uint4*)qf)[((mtb + mt) * 8 + s) * 32 + lane];
                const __half* pb = k_s + (nw * 8 + grp) * KVS + s * 16 + tg * 2;
                uint32_t b0 = *(const uint32_t*)pb;
                uint32_t b1 = *(const uint32_t*)(pb + 8);
#pragma unroll
                for (int mt = 0; mt < 3; mt++)
                    mma_f16(c[mt], av[mt].x, av[mt].y, av[mt].z, av[mt].w, b0, b1);
            }
#pragma unroll
            for (int mt = 0; mt < 3; mt++) {
                int r0 = m0 + mt * 16 + grp, col = nw * 8 + tg * 2;
                *(float2*)&sc[r0 * SCS + col]       = make_float2(c[mt][0], c[mt][1]);
                *(float2*)&sc[(r0 + 8) * SCS + col] = make_float2(c[mt][2], c[mt][3]);
            }
        }
        __syncthreads();

        // ---- online softmax (192 threads, 2 per row, 16 cols each) ----
        if (tid < 192) {
            int row = tid >> 1, half16 = tid & 1;
            bool rowok = masked || ((row >= 48 ? 1 : 0) == (cc >> 1));
            const float* pr = sc + row * SCS + half16 * 16;
            __half* pw_ = ph + row * PHS + half16 * 16;
            int cbase = half16 * 16;
            float mold = m_s[row], cm = mold;
#pragma unroll
            for (int j = 0; j < 16; j++) {
                float s = (rowok && cbase + j < rem) ? pr[j] * SCALE : -1e30f;
                cm = fmaxf(cm, s);
            }
            cm = fmaxf(cm, __shfl_xor_sync(0xffffffffu, cm, 1));
            float corr = __expf(mold - cm);
            float sum = 0.f;
#pragma unroll
            for (int j = 0; j < 16; j++) {
                float e = (rowok && cbase + j < rem) ? __expf(pr[j] * SCALE - cm) : 0.f;
                sum += e;
                pw_[j] = __float2half_rn(e);
            }
            sum += __shfl_xor_sync(0xffffffffu, sum, 1);
            if (half16 == 0) {
                m_s[row] = cm;
                l_s[row] = l_s[row] * corr + sum;
                corr_s[row] = corr;
            }
        }
        __syncthreads();

        // ---- rescale acc + P @ V (warp covers d [nw*32, +32)) ----
#pragma unroll
        for (int mt = 0; mt < 3; mt++) {
            float cr0 = corr_s[m0 + mt * 16 + grp], cr1 = corr_s[m0 + mt * 16 + grp + 8];
#pragma unroll
            for (int nt = 0; nt < 4; nt++) {
                acc[mt][nt][0] *= cr0; acc[mt][nt][1] *= cr0;
                acc[mt][nt][2] *= cr1; acc[mt][nt][3] *= cr1;
            }
        }
        const uint32_t vrow = vb_s + (lane & 15) * (KVS * 2) + (nw * 32) * 2;
#pragma unroll
        for (int ks = 0; ks < 2; ks++) {
            uint32_t af[3][4];
#pragma unroll
            for (int mt = 0; mt < 3; mt++) {
                const __half* p = ph + (m0 + mt * 16 + grp) * PHS + ks * 16 + tg * 2;
                af[mt][0] = *(const uint32_t*)p;
                af[mt][1] = *(const uint32_t*)(p + 8 * PHS);
                af[mt][2] = *(const uint32_t*)(p + 8);
                af[mt][3] = *(const uint32_t*)(p + 8 * PHS + 8);
            }
#pragma unroll
            for (int nt = 0; nt < 4; nt++) {
                uint32_t b0, b1;
                ldmatrix_x2_trans(b0, b1, vrow + ks * 16 * (KVS * 2) + nt * 16);
#pragma unroll
                for (int mt = 0; mt < 3; mt++)
                    mma_f16(acc[mt][nt], af[mt][0], af[mt][1], af[mt][2], af[mt][3], b0, b1);
            }
        }
        __syncthreads();   // K/V + ph consumed -> safe to overwrite

        if (cc + 1 < nch) gather(cc + 1);
    }

    // ---- epilogue: y = acc / l -> half ----
#pragma unroll
    for (int mt = 0; mt < 3; mt++) {
#pragma unroll
        for (int hh = 0; hh < 2; hh++) {
            int r = m0 + mt * 16 + grp + hh * 8;
            int qi = r % 48;
            if (qi < 45) {
                int frame = fp * 2 + (r >= 48 ? 1 : 0);
                float inv = 1.f / l_s[r];
                int y = wy * WH_ + qi / 9, x = wx * WW_ + qi % 9;
                __half* yp = g_yh + ((size_t)(frame * H + y) * W + x) * C
                             + head * HD + nw * 32;
#pragma unroll
                for (int nt = 0; nt < 4; nt++) {
                    float o0 = acc[mt][nt][hh * 2 + 0] * inv;
                    float o1 = acc[mt][nt][hh * 2 + 1] * inv;
                    *(uint32_t*)(yp + nt * 8 + tg * 2) = h2u(o0, o1);
                }
            }
        }
    }
}

// ---------------------------------------------------------------------------
// Launcher
// ---------------------------------------------------------------------------
extern "C" void kernel_launch(void* const* d_in, const int* in_sizes, int n_in,
                              void* d_out, int out_size)
{
    const float* x     = (const float*)d_in[0];
    const float* masks = (const float*)d_in[1];
    const float* Wq    = (const float*)d_in[2];
    const float* bq    = (const float*)d_in[3];
    const float* Wk    = (const float*)d_in[4];
    const float* bk    = (const float*)d_in[5];
    const float* Wv    = (const float*)d_in[6];
    const float* bv    = (const float*)d_in[7];
    const float* Wp    = (const float*)d_in[8];
    const float* bp    = (const float*)d_in[9];
    const float* pw    = (const float*)d_in[10];
    const float* pb    = (const float*)d_in[11];
    float* out = (float*)d_out;

    __half *xh, *qh, *kh, *vh, *yh, *pxh, *pkh, *pvh, *wqh, *wkh, *wvh, *wph;
    cudaGetSymbolAddress((void**)&xh,  g_xh);
    cudaGetSymbolAddress((void**)&qh,  g_qh);
    cudaGetSymbolAddress((void**)&kh,  g_kh);
    cudaGetSymbolAddress((void**)&vh,  g_vh);
    cudaGetSymbolAddress((void**)&yh,  g_yh);
    cudaGetSymbolAddress((void**)&pxh, g_pxh);
    cudaGetSymbolAddress((void**)&pkh, g_pkh);
    cudaGetSymbolAddress((void**)&pvh, g_pvh);
    cudaGetSymbolAddress((void**)&wqh, g_wqh);
    cudaGetSymbolAddress((void**)&wkh, g_wkh);
    cudaGetSymbolAddress((void**)&wvh, g_wvh);
    cudaGetSymbolAddress((void**)&wph, g_wph);

    cudaFuncSetAttribute(gemm_h, cudaFuncAttributeMaxDynamicSharedMemorySize, GH_SMEM);
    cudaFuncSetAttribute(attn_h, cudaFuncAttributeMaxDynamicSharedMemorySize, ATTN_SMEM);

    conv_x_kernel<<<(TOK * C / 4 + 255) / 256, 256>>>(x, xh, TOK * C / 4);
    conv_wT_kernel<<<dim3(16, 16, 4), 256>>>(Wq, Wk, Wv, Wp);

    dim3 gBig(4, TOK / 128);                 // (4, 135)
    dim3 gSm (4, (PTOK + 127) / 128);        // (4, 9)

    gemm_h<<<gBig, 256, GH_SMEM>>>(xh, wqh, bq, qh, nullptr, TOK, 1);
    gemm_h<<<gBig, 256, GH_SMEM>>>(xh, wkh, bk, kh, nullptr, TOK, 1);
    gemm_h<<<gBig, 256, GH_SMEM>>>(xh, wvh, bv, vh, nullptr, TOK, 1);

    pool_kernel<<<T * P_, 256>>>(x, pw, pb);
    gemm_h<<<gSm, 256, GH_SMEM>>>(pxh, wkh, bk, pkh, nullptr, PTOK, 1);
    gemm_h<<<gSm, 256, GH_SMEM>>>(pxh, wvh, bv, pvh, nullptr, PTOK, 1);

    wmask_kernel<<<1, 64>>>(masks);
    init_idx_kernel<<<NWIN, 128>>>();

    attn_h<<<dim3(NWIN, NH, 3), 256, ATTN_SMEM>>>();

    gemm_h<<<gBig, 256, GH_SMEM>>>(yh, wph, bp, nullptr, out, TOK, 0);
}

// round 8
// speedup vs baseline: 9.8451x; 1.6874x over previous
#include <cuda_runtime.h>
#include <cuda_fp16.h>
#include <cstdint>

// ---------------------------------------------------------------------------
// Problem constants
// ---------------------------------------------------------------------------
#define T      6
#define H      40
#define W      72
#define C      512
#define NH     4
#define HD     128
#define WH_    5
#define WW_    9
#define NWIN   64
#define S_     45
#define NROLL  148
#define P_     180
#define KTOT   373
#define TKEYS  (T*KTOT)   // 2238
#define TOK    (T*H*W)    // 17280
#define PTOK   (T*P_)     // 1080
#define SCALE  0.08838834764831845f

// ---------------------------------------------------------------------------
// Scratch (device globals) — fp16 operand tensors
// ---------------------------------------------------------------------------
__device__ __half g_xh[TOK * C];
__device__ __half g_qh[TOK * C];
__device__ __half g_kh[TOK * C];
__device__ __half g_vh[TOK * C];
__device__ __half g_yh[TOK * C];
__device__ __half g_pxh[PTOK * C];
__device__ __half g_pkh[PTOK * C];
__device__ __half g_pvh[PTOK * C];
__device__ __half g_wqh[C * C];   // W^T as half: [n][k]
__device__ __half g_wkh[C * C];
__device__ __half g_wvh[C * C];
__device__ __half g_wph[C * C];
__device__ int    g_widx[NWIN * KTOT];
__device__ int    g_wmask[NWIN];

// ---------------------------------------------------------------------------
// Helpers
// ---------------------------------------------------------------------------
__device__ __forceinline__ void cpasync16(uint32_t dst, const void* src) {
    asm volatile("cp.async.cg.shared.global [%0], [%1], 16;\n"
                 :: "r"(dst), "l"(src));
}

__device__ __forceinline__ void cpasync16z(uint32_t dst, const void* src, int src_sz) {
    asm volatile("cp.async.cg.shared.global [%0], [%1], 16, %2;\n"
                 :: "r"(dst), "l"(src), "r"(src_sz));
}

__device__ __forceinline__ void mma_f16(float* c, uint32_t a0, uint32_t a1,
                                        uint32_t a2, uint32_t a3,
                                        uint32_t b0, uint32_t b1) {
    asm volatile(
        "mma.sync.aligned.m16n8k16.row.col.f32.f16.f16.f32 "
        "{%0,%1,%2,%3}, {%4,%5,%6,%7}, {%8,%9}, {%0,%1,%2,%3};\n"
        : "+f"(c[0]), "+f"(c[1]), "+f"(c[2]), "+f"(c[3])
        : "r"(a0), "r"(a1), "r"(a2), "r"(a3), "r"(b0), "r"(b1));
}

__device__ __forceinline__ void ldmatrix_x2_trans(uint32_t& r0, uint32_t& r1,
                                                  uint32_t addr) {
    asm volatile("ldmatrix.sync.aligned.m8n8.x2.trans.shared.b16 {%0,%1}, [%2];"
                 : "=r"(r0), "=r"(r1) : "r"(addr));
}

__device__ __forceinline__ uint32_t smem_u32(const void* p) {
    return (uint32_t)__cvta_generic_to_shared(p);
}

__device__ __forceinline__ uint32_t h2u(float a, float b) {
    __half2 h = __floats2half2_rn(a, b);
    return *(uint32_t*)&h;
}

// ---------------------------------------------------------------------------
// Conversions
// ---------------------------------------------------------------------------
__global__ void conv_x_kernel(const float* __restrict__ in,
                              __half* __restrict__ out, int n4) {
    int i = blockIdx.x * blockDim.x + threadIdx.x;
    if (i < n4) {
        float4 v = ((const float4*)in)[i];
        ((uint32_t*)out)[i * 2 + 0] = h2u(v.x, v.y);
        ((uint32_t*)out)[i * 2 + 1] = h2u(v.z, v.w);
    }
}

__global__ void conv_wT_kernel(const float* __restrict__ w0, const float* __restrict__ w1,
                               const float* __restrict__ w2, const float* __restrict__ w3)
{
    __shared__ float t[32][33];
    const float* src[4] = {w0, w1, w2, w3};
    __half* dst[4] = {g_wqh, g_wkh, g_wvh, g_wph};
    int m = blockIdx.z;
    int bx = blockIdx.x * 32, by = blockIdx.y * 32;
    int tx = threadIdx.x & 31, ty0 = threadIdx.x >> 5;
#pragma unroll
    for (int i = 0; i < 4; i++) {
        int ty = ty0 + i * 8;
        t[ty][tx] = src[m][(size_t)(by + ty) * C + bx + tx];
    }
    __syncthreads();
#pragma unroll
    for (int i = 0; i < 4; i++) {
        int ty = ty0 + i * 8;
        dst[m][(size_t)(bx + ty) * C + by + tx] = __float2half_rn(t[tx][ty]);
    }
}

// ---------------------------------------------------------------------------
// fp16 GEMM (R7 proven): C[M,512] = A[M,512] @ W[512,512] + bias
// ---------------------------------------------------------------------------
#define GH_ROW   72
#define GH_TILEB (128 * GH_ROW * 2)
#define GH_SMEM  (4 * GH_TILEB)

__global__ __launch_bounds__(256, 2) void gemm_h(
    const __half* __restrict__ A, const __half* __restrict__ Bt,
    const float* __restrict__ bias, __half* __restrict__ Ch,
    float* __restrict__ Cf, int M, int write_half)
{
    extern __shared__ char smc[];
    __half* a_sm = (__half*)smc;
    __half* b_sm = (__half*)(smc + 2 * GH_TILEB);
    const int tid  = threadIdx.x;
    const int lane = tid & 31, warp = tid >> 5;
    const int grp  = lane >> 2, tg = lane & 3;
    const int mb = (warp >> 2) * 64, nb = (warp & 3) * 32;
    const int row0 = blockIdx.y * 128, col0 = blockIdx.x * 128;

    const uint32_t sA = smem_u32(a_sm);
    const uint32_t sB = smem_u32(b_sm);

    float acc[4][4][4];
#pragma unroll
    for (int i = 0; i < 4; i++)
#pragma unroll
        for (int j = 0; j < 4; j++)
#pragma unroll
            for (int r = 0; r < 4; r++) acc[i][j][r] = 0.f;

    auto load_tile = [&](int kt, int b) {
#pragma unroll
        for (int i = 0; i < 4; i++) {
            int idx = i * 256 + tid;
            int r = idx >> 3, seg = idx & 7;
            int gr = row0 + r; if (gr > M - 1) gr = M - 1;
            cpasync16(sA + b * GH_TILEB + r * (GH_ROW * 2) + seg * 16,
                      A + (size_t)gr * 512 + kt * 64 + seg * 8);
        }
#pragma unroll
        for (int i = 0; i < 4; i++) {
            int idx = i * 256 + tid;
            int r = idx >> 3, seg = idx & 7;
            cpasync16(sB + b * GH_TILEB + r * (GH_ROW * 2) + seg * 16,
                      Bt + (size_t)(col0 + r) * 512 + kt * 64 + seg * 8);
        }
        asm volatile("cp.async.commit_group;\n");
    };

    load_tile(0, 0);

    for (int it = 0; it < 8; it++) {
        if (it < 7) {
            load_tile(it + 1, (it & 1) ^ 1);
            asm volatile("cp.async.wait_group 1;\n");
        } else {
            asm volatile("cp.async.wait_group 0;\n");
        }
        __syncthreads();
        const __half* at = a_sm + (it & 1) * 128 * GH_ROW;
        const __half* bt = b_sm + (it & 1) * 128 * GH_ROW;
#pragma unroll
        for (int s = 0; s < 4; s++) {
            uint32_t af[4][4];
#pragma unroll
            for (int mt = 0; mt < 4; mt++) {
                const __half* p = at + (mb + mt * 16 + grp) * GH_ROW + s * 16 + tg * 2;
                af[mt][0] = *(const uint32_t*)p;
                af[mt][1] = *(const uint32_t*)(p + 8 * GH_ROW);
                af[mt][2] = *(const uint32_t*)(p + 8);
                af[mt][3] = *(const uint32_t*)(p + 8 * GH_ROW + 8);
            }
#pragma unroll
            for (int nt = 0; nt < 4; nt++) {
                const __half* pb = bt + (nb + nt * 8 + grp) * GH_ROW + s * 16 + tg * 2;
                uint32_t b0 = *(const uint32_t*)pb;
                uint32_t b1 = *(const uint32_t*)(pb + 8);
#pragma unroll
                for (int mt = 0; mt < 4; mt++)
                    mma_f16(acc[mt][nt], af[mt][0], af[mt][1], af[mt][2], af[mt][3], b0, b1);
            }
        }
        __syncthreads();
    }

#pragma unroll
    for (int mt = 0; mt < 4; mt++) {
        int r0 = row0 + mb + mt * 16 + grp;
#pragma unroll
        for (int nt = 0; nt < 4; nt++) {
            int cc = col0 + nb + nt * 8 + tg * 2;
            float b0v = bias[cc], b1v = bias[cc + 1];
            float o0 = acc[mt][nt][0] + b0v, o1 = acc[mt][nt][1] + b1v;
            float o2 = acc[mt][nt][2] + b0v, o3 = acc[mt][nt][3] + b1v;
            if (write_half) {
                if (r0 < M)     *(uint32_t*)&Ch[(size_t)r0 * 512 + cc]       = h2u(o0, o1);
                if (r0 + 8 < M) *(uint32_t*)&Ch[(size_t)(r0 + 8) * 512 + cc] = h2u(o2, o3);
            } else {
                if (r0 < M)     *(float2*)(Cf + (size_t)r0 * 512 + cc)       = make_float2(o0, o1);
                if (r0 + 8 < M) *(float2*)(Cf + (size_t)(r0 + 8) * 512 + cc) = make_float2(o2, o3);
            }
        }
    }
}

// ---------------------------------------------------------------------------
// Depthwise pool conv -> half px
// ---------------------------------------------------------------------------
__global__ void pool_kernel(const float* __restrict__ x,
                            const float* __restrict__ pw,
                            const float* __restrict__ pb)
{
    int o = blockIdx.x;
    int f = o / 180, r = o % 180;
    int py = r / 18, pxx = r % 18;
    for (int c = threadIdx.x; c < C; c += blockDim.x) {
        float s = pb[c];
#pragma unroll
        for (int i = 0; i < 4; i++)
#pragma unroll
            for (int j = 0; j < 4; j++)
                s += x[((size_t)(f * H + py * 4 + i) * W + (pxx * 4 + j)) * C + c]
                     * pw[(i * 4 + j) * C + c];
        g_pxh[(size_t)o * C + c] = __float2half_rn(s);
    }
}

// ---------------------------------------------------------------------------
// Window mask + key index table
// ---------------------------------------------------------------------------
__global__ void wmask_kernel(const float* __restrict__ masks)
{
    int win = threadIdx.x;
    if (win >= NWIN) return;
    int wy = win >> 3, wx = win & 7;
    float s = 0.f;
    for (int f = 0; f < T; f++)
        for (int i = 0; i < WH_; i++)
            for (int j = 0; j < WW_; j++)
                s += masks[(size_t)(f * H + wy * WH_ + i) * W + (wx * WW_ + j)];
    g_wmask[win] = (s > 0.f) ? 1 : 0;
}

__global__ void init_idx_kernel()
{
    __shared__ int vind[NROLL];
    if (threadIdx.x == 0) {
        int cnt = 0;
        for (int s = 0; s < 4; s++)
            for (int i = 0; i < WH_; i++)
                for (int j = 0; j < WW_; j++) {
                    bool inval;
                    if (s == 0)      inval = (i < 2 && j < 4);
                    else if (s == 1) inval = (i < 2 && j >= 5);
                    else if (s == 2) inval = (i >= 3 && j < 4);
                    else             inval = (i >= 3 && j >= 5);
                    if (!inval) vind[cnt++] = s * 45 + i * 9 + j;
                }
    }
    __syncthreads();
    int win = blockIdx.x;
    int wy = win >> 3, wx = win & 7;
    for (int j = threadIdx.x; j < KTOT; j += blockDim.x) {
        int val;
        if (j < S_) {
            int i = j / 9, jj = j % 9;
            val = (wy * WH_ + i) * W + (wx * WW_ + jj);
        } else if (j < S_ + NROLL) {
            int v = vind[j - S_];
            int s = v / 45, pos = v % 45;
            int i = pos / 9, jj = pos % 9;
            int s0 = (s < 2) ? -3 : 3;
            int s1 = ((s & 1) == 0) ? -5 : 5;
            int y = wy * WH_ + i, x = wx * WW_ + jj;
            int yy = ((y - s0) % H + H) % H;
            int xx = ((x - s1) % W + W) % W;
            val = yy * W + xx;
        } else {
            val = -(j - (S_ + NROLL)) - 1;
        }
        g_widx[win * KTOT + j] = val;
    }
}

// ---------------------------------------------------------------------------
// Attention v5: register-resident flash. block=(win, head, frame-pair),
// 192 threads / 6 warps (1 m16 row-tile each). KC=64 double-buffered K/V.
// QK scores -> register softmax (shfl over tg) -> half A-frags -> PV.
// m/l in registers. ONE __syncthreads per chunk. smem 92KB, 2 blocks/SM.
// ---------------------------------------------------------------------------
#define KVS2 136
#define KC   64
#define QF_BYTES 24576
#define KBUF (KC * KVS2 * 2)            // 17408 bytes per buffer
#define ATTN_SMEM (QF_BYTES + 4 * KBUF) // 94208

__global__ __launch_bounds__(192, 2) void attn_h()
{
    const int win = blockIdx.x, head = blockIdx.y, fp = blockIdx.z;
    const int tid  = threadIdx.x;
    const int lane = tid & 31, w = tid >> 5;     // w = row-tile 0..5
    const int grp  = lane >> 2, tg = lane & 3;
    extern __shared__ char smc[];
    uint32_t* qf  = (uint32_t*)smc;                       // [6][8][32][4] u32
    __half*   k_s = (__half*)(smc + QF_BYTES);            // [2][64][136]
    __half*   v_s = (__half*)(smc + QF_BYTES + 2 * KBUF); // [2][64][136]
    const uint32_t kb = smem_u32(k_s), vb = smem_u32(v_s);

    const int wy = win >> 3, wx = win & 7;
    const int masked = g_wmask[win];
    const int nch    = masked ? (TKEYS + KC - 1) / KC : 2;   // 35 or 2
    const int* widx  = g_widx + win * KTOT;

    // ---- load Q (pre-scaled) into fragment-packed layout ----
    const __half2 sc2 = __floats2half2_rn(SCALE, SCALE);
    for (int idx = tid; idx < 96 * 16; idx += 192) {
        int row = idx >> 4, seg8 = idx & 15;
        int qi = row % 48;
        int frame = fp * 2 + (row >= 48 ? 1 : 0);
        uint4 v = make_uint4(0u, 0u, 0u, 0u);
        if (qi < 45) {
            int y = wy * WH_ + qi / 9, x = wx * WW_ + qi % 9;
            v = *(const uint4*)(g_qh + ((size_t)(frame * H + y) * W + x) * C
                                + head * HD + seg8 * 8);
            __half2* hh = (__half2*)&v;
            hh[0] = __hmul2(hh[0], sc2); hh[1] = __hmul2(hh[1], sc2);
            hh[2] = __hmul2(hh[2], sc2); hh[3] = __hmul2(hh[3], sc2);
        }
        int mt = row >> 4, rr = row & 15;
        int rg = rr & 7, hi = rr >> 3;
        int s = seg8 >> 1, lo8 = seg8 & 1;
        int comp = hi + 2 * lo8;
        uint32_t* base = qf + ((mt * 8 + s) * 32 + rg * 4) * 4 + comp;
        base[0]  = v.x;
        base[4]  = v.y;
        base[8]  = v.z;
        base[12] = v.w;
    }

    float acc[16][4];
#pragma unroll
    for (int i = 0; i < 16; i++)
#pragma unroll
        for (int r = 0; r < 4; r++) acc[i][r] = 0.f;
    float m0 = -1e30f, m1 = -1e30f, l0 = 0.f, l1 = 0.f;

    // ---- gather chunk cc into buffer buf ----
    auto gather = [&](int cc, int buf) {
        for (int e = tid; e < KC * 16; e += 192) {
            int key = e >> 4, seg = e & 15;
            const __half *ksrc = g_kh, *vsrc = g_kh;
            int sz = 0;
            bool valid;
            int f2, j;
            if (masked) {
                int g = cc * KC + key;
                valid = (g < TKEYS);
                f2 = g / KTOT; j = g - f2 * KTOT;
            } else {
                j = key;
                valid = (key < S_);
                f2 = fp * 2 + cc;
            }
            if (valid) {
                int id = widx[j];
                size_t off;
                if (id >= 0) {
                    off = ((size_t)(f2 * (H * W) + id)) * C + head * HD + seg * 8;
                    ksrc = g_kh + off; vsrc = g_vh + off;
                } else {
                    off = ((size_t)(f2 * P_ + (-id - 1))) * C + head * HD + seg * 8;
                    ksrc = g_pkh + off; vsrc = g_pvh + off;
                }
                sz = 16;
            }
            uint32_t d = (uint32_t)(buf * KBUF + key * (KVS2 * 2) + seg * 16);
            cpasync16z(kb + d, ksrc, sz);
            cpasync16z(vb + d, vsrc, sz);
        }
        asm volatile("cp.async.commit_group;\n");
    };

    gather(0, 0);

    for (int cc = 0; cc < nch; cc++) {
        asm volatile("cp.async.wait_group 0;\n");
        __syncthreads();   // buf[cc&1] ready; all warps done with buf[cc-1]
        const int buf = cc & 1;
        if (cc + 1 < nch) gather(cc + 1, buf ^ 1);

        // unmasked: chunk 0 feeds rows 0-47 (warps 0-2), chunk 1 rows 48-95
        if (masked || ((w >= 3) == (cc == 1))) {
            const int rem = masked ? min(KC, TKEYS - cc * KC) : S_;
            const __half* kc = k_s + buf * KC * KVS2;
            const uint32_t vbc = vb + buf * KBUF;

            // ---- QK^T: 16 rows x 64 keys, k=128 ----
            float c[8][4];
#pragma unroll
            for (int nt = 0; nt < 8; nt++)
#pragma unroll
                for (int r = 0; r < 4; r++) c[nt][r] = 0.f;
#pragma unroll
            for (int s = 0; s < 8; s++) {
                uint4 a = ((const uint4*)qf)[(w * 8 + s) * 32 + lane];
#pragma unroll
                for (int nt = 0; nt < 8; nt++) {
                    const __half* pb = kc + (nt * 8 + grp) * KVS2 + s * 16 + tg * 2;
                    uint32_t b0 = *(const uint32_t*)pb;
                    uint32_t b1 = *(const uint32_t*)(pb + 8);
                    mma_f16(c[nt], a.x, a.y, a.z, a.w, b0, b1);
                }
            }

            // ---- clamp invalid key columns ----
#pragma unroll
            for (int nt = 0; nt < 8; nt++) {
                int k0 = nt * 8 + tg * 2;
                if (k0 >= rem)     { c[nt][0] = -1e30f; c[nt][2] = -1e30f; }
                if (k0 + 1 >= rem) { c[nt][1] = -1e30f; c[nt][3] = -1e30f; }
            }

            // ---- register softmax (rows grp, grp+8) ----
            float r0 = -1e30f, r1 = -1e30f;
#pragma unroll
            for (int nt = 0; nt < 8; nt++) {
                r0 = fmaxf(r0, fmaxf(c[nt][0], c[nt][1]));
                r1 = fmaxf(r1, fmaxf(c[nt][2], c[nt][3]));
            }
            r0 = fmaxf(r0, __shfl_xor_sync(0xffffffffu, r0, 1));
            r0 = fmaxf(r0, __shfl_xor_sync(0xffffffffu, r0, 2));
            r1 = fmaxf(r1, __shfl_xor_sync(0xffffffffu, r1, 1));
            r1 = fmaxf(r1, __shfl_xor_sync(0xffffffffu, r1, 2));
            float m0n = fmaxf(m0, r0), m1n = fmaxf(m1, r1);

            float s0 = 0.f, s1 = 0.f;
            uint32_t pk[8][2];
#pragma unroll
            for (int nt = 0; nt < 8; nt++) {
                float p0 = __expf(c[nt][0] - m0n);
                float p1 = __expf(c[nt][1] - m0n);
                float p2 = __expf(c[nt][2] - m1n);
                float p3 = __expf(c[nt][3] - m1n);
                s0 += p0 + p1; s1 += p2 + p3;
                pk[nt][0] = h2u(p0, p1);
                pk[nt][1] = h2u(p2, p3);
            }
            s0 += __shfl_xor_sync(0xffffffffu, s0, 1);
            s0 += __shfl_xor_sync(0xffffffffu, s0, 2);
            s1 += __shfl_xor_sync(0xffffffffu, s1, 1);
            s1 += __shfl_xor_sync(0xffffffffu, s1, 2);

            float corr0 = __expf(m0 - m0n), corr1 = __expf(m1 - m1n);
            l0 = l0 * corr0 + s0;
            l1 = l1 * corr1 + s1;
            bool same = (m0n == m0) && (m1n == m1);
            if (!__all_sync(0xffffffffu, same)) {
#pragma unroll
                for (int nt2 = 0; nt2 < 16; nt2++) {
                    acc[nt2][0] *= corr0; acc[nt2][1] *= corr0;
                    acc[nt2][2] *= corr1; acc[nt2][3] *= corr1;
                }
            }
            m0 = m0n; m1 = m1n;

            // ---- PV: 16 rows x 128 dims, k=64 keys ----
            const uint32_t vrow = vbc + (lane & 15) * (KVS2 * 2);
#pragma unroll
            for (int ks = 0; ks < 4; ks++) {
                uint32_t a0 = pk[2 * ks][0],     a1 = pk[2 * ks][1];
                uint32_t a2 = pk[2 * ks + 1][0], a3 = pk[2 * ks + 1][1];
#pragma unroll
                for (int nt2 = 0; nt2 < 16; nt2++) {
                    uint32_t b0, b1;
                    ldmatrix_x2_trans(b0, b1, vrow + ks * 16 * (KVS2 * 2) + nt2 * 16);
                    mma_f16(acc[nt2], a0, a1, a2, a3, b0, b1);
                }
            }
        }
    }

    // ---- epilogue: y = acc / l -> half ----
#pragma unroll
    for (int hh = 0; hh < 2; hh++) {
        int row = w * 16 + grp + hh * 8;
        int qi = row % 48;
        if (qi < 45) {
            int frame = fp * 2 + (row >= 48 ? 1 : 0);
            float inv = 1.f / (hh ? l1 : l0);
            int y = wy * WH_ + qi / 9, x = wx * WW_ + qi % 9;
            __half* yp = g_yh + ((size_t)(frame * H + y) * W + x) * C + head * HD;
#pragma unroll
            for (int nt2 = 0; nt2 < 16; nt2++) {
                float o0 = acc[nt2][hh * 2 + 0] * inv;
                float o1 = acc[nt2][hh * 2 + 1] * inv;
                *(uint32_t*)(yp + nt2 * 8 + tg * 2) = h2u(o0, o1);
            }
        }
    }
}

// ---------------------------------------------------------------------------
// Launcher
// ---------------------------------------------------------------------------
extern "C" void kernel_launch(void* const* d_in, const int* in_sizes, int n_in,
                              void* d_out, int out_size)
{
    const float* x     = (const float*)d_in[0];
    const float* masks = (const float*)d_in[1];
    const float* Wq    = (const float*)d_in[2];
    const float* bq    = (const float*)d_in[3];
    const float* Wk    = (const float*)d_in[4];
    const float* bk    = (const float*)d_in[5];
    const float* Wv    = (const float*)d_in[6];
    const float* bv    = (const float*)d_in[7];
    const float* Wp    = (const float*)d_in[8];
    const float* bp    = (const float*)d_in[9];
    const float* pw    = (const float*)d_in[10];
    const float* pb    = (const float*)d_in[11];
    float* out = (float*)d_out;

    __half *xh, *qh, *kh, *vh, *yh, *pxh, *pkh, *pvh, *wqh, *wkh, *wvh, *wph;
    cudaGetSymbolAddress((void**)&xh,  g_xh);
    cudaGetSymbolAddress((void**)&qh,  g_qh);
    cudaGetSymbolAddress((void**)&kh,  g_kh);
    cudaGetSymbolAddress((void**)&vh,  g_vh);
    cudaGetSymbolAddress((void**)&yh,  g_yh);
    cudaGetSymbolAddress((void**)&pxh, g_pxh);
    cudaGetSymbolAddress((void**)&pkh, g_pkh);
    cudaGetSymbolAddress((void**)&pvh, g_pvh);
    cudaGetSymbolAddress((void**)&wqh, g_wqh);
    cudaGetSymbolAddress((void**)&wkh, g_wkh);
    cudaGetSymbolAddress((void**)&wvh, g_wvh);
    cudaGetSymbolAddress((void**)&wph, g_wph);

    cudaFuncSetAttribute(gemm_h, cudaFuncAttributeMaxDynamicSharedMemorySize, GH_SMEM);
    cudaFuncSetAttribute(attn_h, cudaFuncAttributeMaxDynamicSharedMemorySize, ATTN_SMEM);

    conv_x_kernel<<<(TOK * C / 4 + 255) / 256, 256>>>(x, xh, TOK * C / 4);
    conv_wT_kernel<<<dim3(16, 16, 4), 256>>>(Wq, Wk, Wv, Wp);

    dim3 gBig(4, TOK / 128);                 // (4, 135)
    dim3 gSm (4, (PTOK + 127) / 128);        // (4, 9)

    gemm_h<<<gBig, 256, GH_SMEM>>>(xh, wqh, bq, qh, nullptr, TOK, 1);
    gemm_h<<<gBig, 256, GH_SMEM>>>(xh, wkh, bk, kh, nullptr, TOK, 1);
    gemm_h<<<gBig, 256, GH_SMEM>>>(xh, wvh, bv, vh, nullptr, TOK, 1);

    pool_kernel<<<T * P_, 256>>>(x, pw, pb);
    gemm_h<<<gSm, 256, GH_SMEM>>>(pxh, wkh, bk, pkh, nullptr, PTOK, 1);
    gemm_h<<<gSm, 256, GH_SMEM>>>(pxh, wvh, bv, pvh, nullptr, PTOK, 1);

    wmask_kernel<<<1, 64>>>(masks);
    init_idx_kernel<<<NWIN, 128>>>();

    attn_h<<<dim3(NWIN, NH, 3), 192, ATTN_SMEM>>>();

    gemm_h<<<gBig, 256, GH_SMEM>>>(yh, wph, bp, nullptr, out, TOK, 0);
}